// round 5
// baseline (speedup 1.0000x reference)
#include <cuda_runtime.h>
#include <math.h>
#include <stdint.h>

// Problem constants
#define BN  32768
#define DIM 256
#define NK  32
#define NH  8
#define NFF 1024
#define NDK 32

// ---------------- scratch (device globals: allocation-guard-safe) ----------------
__device__ __align__(128) float g_lnx[BN * DIM];        // LN1(x_anc)
__device__ __align__(128) float g_q[BN * DIM];          // Q
__device__ __align__(128) float g_qt[BN * NH * DIM];    // q~ [B, H, 256]
__device__ __align__(128) float g_ctx[BN * NH * DIM];   // ctx [B, H, 256]
__device__ __align__(128) float g_att[BN * DIM];        // attention output (pre-W_o)
__device__ __align__(128) float g_x[BN * DIM];          // x = x_anc + att @ W_o
__device__ __align__(128) float g_h[BN * DIM];          // LN2(x)
__device__ __align__(128) float g_ff[BN * NFF];         // gelu(h@ff1+b1)

// ---------------- LayerNorm: one warp per row ----------------
__global__ void ln_kernel(const float* __restrict__ x, const float* __restrict__ g,
                          const float* __restrict__ b, float* __restrict__ out) {
    int row  = blockIdx.x * 8 + threadIdx.y;
    int lane = threadIdx.x;
    const float4* xr = reinterpret_cast<const float4*>(x + (size_t)row * DIM);
    float4 v0 = xr[lane];
    float4 v1 = xr[lane + 32];
    float s  = v0.x + v0.y + v0.z + v0.w + v1.x + v1.y + v1.z + v1.w;
    float ss = v0.x*v0.x + v0.y*v0.y + v0.z*v0.z + v0.w*v0.w
             + v1.x*v1.x + v1.y*v1.y + v1.z*v1.z + v1.w*v1.w;
    #pragma unroll
    for (int o = 16; o; o >>= 1) {
        s  += __shfl_xor_sync(0xFFFFFFFFu, s,  o);
        ss += __shfl_xor_sync(0xFFFFFFFFu, ss, o);
    }
    float mu  = s * (1.0f / 256.0f);
    float var = ss * (1.0f / 256.0f) - mu * mu;
    float rs  = rsqrtf(var + 1e-5f);
    const float4* g4 = reinterpret_cast<const float4*>(g);
    const float4* b4 = reinterpret_cast<const float4*>(b);
    float4* orow = reinterpret_cast<float4*>(out + (size_t)row * DIM);
    #pragma unroll
    for (int p = 0; p < 2; p++) {
        int idx = lane + p * 32;
        float4 v = (p == 0) ? v0 : v1;
        float4 gg = g4[idx], bb = b4[idx];
        float4 o4;
        o4.x = (v.x - mu) * rs * gg.x + bb.x;
        o4.y = (v.y - mu) * rs * gg.y + bb.y;
        o4.z = (v.z - mu) * rs * gg.z + bb.z;
        o4.w = (v.w - mu) * rs * gg.w + bb.w;
        orow[idx] = o4;
    }
}

__device__ __forceinline__ float gelu_exact(float v) {
    return 0.5f * v * (1.0f + erff(v * 0.70710678118654752f));
}

// ---------------- tf32 tensor-core GEMM: 128x128x16, A k-pair-interleaved ----------------
// MODE 0: C = A@B
// MODE 1: C = gelu(A@B + bias)
// MODE 2: C = A@B + bias + resid
// MODE 3: C = A@B + resid
__device__ __forceinline__ void mma_tf32(float c[4], const uint32_t a[4], const uint32_t b[2]) {
    asm volatile(
        "mma.sync.aligned.m16n8k8.row.col.f32.tf32.tf32.f32 "
        "{%0,%1,%2,%3}, {%4,%5,%6,%7}, {%8,%9}, {%0,%1,%2,%3};\n"
        : "+f"(c[0]), "+f"(c[1]), "+f"(c[2]), "+f"(c[3])
        : "r"(a[0]), "r"(a[1]), "r"(a[2]), "r"(a[3]), "r"(b[0]), "r"(b[1]));
}

template <int MODE>
__global__ __launch_bounds__(256, 2)
void tgemm(const float* __restrict__ A, const float* __restrict__ Bw,
           float* __restrict__ C, int M, int N, int Kd,
           const float* __restrict__ bias, const float* __restrict__ resid) {
    // As: k-pair-interleaved. Float offset (ks + 2*fc) within a row holds the
    // pair (k = ks+fc, k = ks+fc+4). Stride 24 floats (12 pairs): frag LDS.64
    // pair-address = r*12 + ks/2 + fc -> conflict-free per half-warp phase.
    __shared__ float As[2][128][24];
    __shared__ float Bs[2][16][136];

    const int tid  = threadIdx.x;
    const int lane = tid & 31;
    const int wid  = tid >> 5;
    const int m0 = blockIdx.y * 128;
    const int n0 = blockIdx.x * 128;
    const int warp_m = (wid & 1) * 64;
    const int warp_n = (wid >> 1) * 32;

    // global-load assignments
    const int aRow = tid >> 1;            // 0..127
    const int aCol = (tid & 1) * 8;       // 0 or 8 (float offset of the pair region)
    const int bRow = tid >> 4;            // 0..15
    const int bCol = (tid & 15) * 4;      // 0..60

    const float* Ag = A  + (size_t)(m0 + aRow) * Kd + aCol;
    const float* Bg = Bw + (size_t)bRow * N + n0 + bCol;

    float c[4][4][4];
    #pragma unroll
    for (int mt = 0; mt < 4; mt++)
        #pragma unroll
        for (int nt = 0; nt < 4; nt++)
            #pragma unroll
            for (int i = 0; i < 4; i++) c[mt][nt][i] = 0.0f;

    // prologue: load k-tile 0 into buffer 0
    float4 a0 = *reinterpret_cast<const float4*>(Ag);       // k = aCol..aCol+3
    float4 a1 = *reinterpret_cast<const float4*>(Ag + 4);   // k = aCol+4..aCol+7
    float4 b0 = *reinterpret_cast<const float4*>(Bg);
    float4 b1 = *reinterpret_cast<const float4*>(Bg + 64);
    {
        float* Ad = &As[0][aRow][aCol];
        *reinterpret_cast<float2*>(Ad + 0) = make_float2(a0.x, a1.x);
        *reinterpret_cast<float2*>(Ad + 2) = make_float2(a0.y, a1.y);
        *reinterpret_cast<float2*>(Ad + 4) = make_float2(a0.z, a1.z);
        *reinterpret_cast<float2*>(Ad + 6) = make_float2(a0.w, a1.w);
    }
    *reinterpret_cast<float4*>(&Bs[0][bRow][bCol])      = b0;
    *reinterpret_cast<float4*>(&Bs[0][bRow][bCol + 64]) = b1;
    __syncthreads();

    const int KT = Kd >> 4;
    int buf = 0;
    const int fr = lane >> 2;     // 0..7
    const int fc = lane & 3;      // 0..3

    for (int kt = 0; kt < KT; kt++) {
        if (kt + 1 < KT) {
            const float* Ap = Ag + (kt + 1) * 16;
            const float* Bp = Bg + (size_t)(kt + 1) * 16 * N;
            a0 = *reinterpret_cast<const float4*>(Ap);
            a1 = *reinterpret_cast<const float4*>(Ap + 4);
            b0 = *reinterpret_cast<const float4*>(Bp);
            b1 = *reinterpret_cast<const float4*>(Bp + 64);
        }
        #pragma unroll
        for (int ks = 0; ks < 16; ks += 8) {
            uint32_t af[4][4];
            uint32_t bf[4][2];
            #pragma unroll
            for (int mt = 0; mt < 4; mt++) {
                int r = warp_m + mt * 16 + fr;
                float2 pa = *reinterpret_cast<const float2*>(&As[buf][r][ks + 2 * fc]);
                float2 pb = *reinterpret_cast<const float2*>(&As[buf][r + 8][ks + 2 * fc]);
                af[mt][0] = __float_as_uint(pa.x);   // k = ks+fc,   row r
                af[mt][1] = __float_as_uint(pb.x);   // k = ks+fc,   row r+8
                af[mt][2] = __float_as_uint(pa.y);   // k = ks+fc+4, row r
                af[mt][3] = __float_as_uint(pb.y);   // k = ks+fc+4, row r+8
            }
            #pragma unroll
            for (int nt = 0; nt < 4; nt++) {
                int cn = warp_n + nt * 8 + fr;
                bf[nt][0] = __float_as_uint(Bs[buf][ks + fc][cn]);
                bf[nt][1] = __float_as_uint(Bs[buf][ks + 4 + fc][cn]);
            }
            #pragma unroll
            for (int mt = 0; mt < 4; mt++)
                #pragma unroll
                for (int nt = 0; nt < 4; nt++)
                    mma_tf32(c[mt][nt], af[mt], bf[nt]);
        }
        if (kt + 1 < KT) {
            buf ^= 1;
            float* Ad = &As[buf][aRow][aCol];
            *reinterpret_cast<float2*>(Ad + 0) = make_float2(a0.x, a1.x);
            *reinterpret_cast<float2*>(Ad + 2) = make_float2(a0.y, a1.y);
            *reinterpret_cast<float2*>(Ad + 4) = make_float2(a0.z, a1.z);
            *reinterpret_cast<float2*>(Ad + 6) = make_float2(a0.w, a1.w);
            *reinterpret_cast<float4*>(&Bs[buf][bRow][bCol])      = b0;
            *reinterpret_cast<float4*>(&Bs[buf][bRow][bCol + 64]) = b1;
        }
        __syncthreads();
    }

    // epilogue
    #pragma unroll
    for (int mt = 0; mt < 4; mt++) {
        #pragma unroll
        for (int nt = 0; nt < 4; nt++) {
            int row0 = m0 + warp_m + mt * 16 + fr;
            int col  = n0 + warp_n + nt * 8 + fc * 2;
            float v0 = c[mt][nt][0], v1 = c[mt][nt][1];
            float v2 = c[mt][nt][2], v3 = c[mt][nt][3];
            if (MODE == 1 || MODE == 2) {
                float2 bv = *reinterpret_cast<const float2*>(bias + col);
                v0 += bv.x; v1 += bv.y; v2 += bv.x; v3 += bv.y;
            }
            if (MODE == 1) {
                v0 = gelu_exact(v0); v1 = gelu_exact(v1);
                v2 = gelu_exact(v2); v3 = gelu_exact(v3);
            }
            if (MODE == 2 || MODE == 3) {
                float2 r0 = *reinterpret_cast<const float2*>(resid + (size_t)row0 * N + col);
                float2 r1 = *reinterpret_cast<const float2*>(resid + (size_t)(row0 + 8) * N + col);
                v0 += r0.x; v1 += r0.y; v2 += r1.x; v3 += r1.y;
            }
            float2 o0 = make_float2(v0, v1);
            float2 o1 = make_float2(v2, v3);
            *reinterpret_cast<float2*>(C + (size_t)row0 * N + col)       = o0;
            *reinterpret_cast<float2*>(C + (size_t)(row0 + 8) * N + col) = o1;
        }
    }
}

// ---------------- q~[b,h,d] = sum_j Q[b, h*32+j] * W_k[d, h*32+j] ----------------
__global__ void qtilde_kernel(const float* __restrict__ Q, const float* __restrict__ Wk,
                              float* __restrict__ qt) {
    __shared__ float Wks[256 * 33];
    __shared__ float Qs[8 * 32];
    int h  = blockIdx.y;
    int b0 = blockIdx.x * 8;
    int tid = threadIdx.x;
    for (int i = tid; i < 8192; i += 256) {
        int d = i >> 5, j = i & 31;
        Wks[d * 33 + j] = Wk[d * 256 + h * 32 + j];
    }
    {
        int r = tid >> 5, j = tid & 31;
        Qs[tid] = Q[(size_t)(b0 + r) * 256 + h * 32 + j];
    }
    __syncthreads();
    int d = tid;
    float w[32];
    #pragma unroll
    for (int j = 0; j < 32; j++) w[j] = Wks[d * 33 + j];
    float acc[8];
    #pragma unroll
    for (int r = 0; r < 8; r++) acc[r] = 0.0f;
    const float4* Qs4 = reinterpret_cast<const float4*>(Qs);
    #pragma unroll
    for (int r = 0; r < 8; r++) {
        #pragma unroll
        for (int j4 = 0; j4 < 8; j4++) {
            float4 q = Qs4[r * 8 + j4];
            acc[r] += q.x * w[j4 * 4 + 0] + q.y * w[j4 * 4 + 1]
                    + q.z * w[j4 * 4 + 2] + q.w * w[j4 * 4 + 3];
        }
    }
    #pragma unroll
    for (int r = 0; r < 8; r++)
        qt[(size_t)(b0 + r) * 2048 + h * 256 + d] = acc[r];
}

// ---------------- attention core v4b, one block per anchor b ----------------
// Phase1: warp = d-eighth x all 8 heads (x float4 feeds 8 dot chains; q smem broadcast).
// Phase2: warp = (4-head group, d-quarter); x float2 feeds 4 heads.
__global__ __launch_bounds__(256, 4)
void attn_kernel(const float* __restrict__ xnei, const float* __restrict__ qt,
                 float* __restrict__ ctx) {
    __shared__ float xs[32 * 260];   // stride 260: conflict-free float4/float2 row access
    __shared__ float qts[8 * 260];   // stride 260: conflict-free broadcasts
    __shared__ float sred[8 * 256];  // [w-slice][h*32+k]
    __shared__ float attns[8 * 32];
    int b    = blockIdx.x;
    int tid  = threadIdx.x;
    int lane = tid & 31;
    int w    = tid >> 5;

    // stage x_nei[b] : 32 x 256 floats
    const float4* xb4 = reinterpret_cast<const float4*>(xnei + (size_t)b * 8192);
    #pragma unroll
    for (int j = 0; j < 8; j++) {
        int i  = tid + j * 256;
        int k  = i >> 6;
        int c4 = i & 63;
        *reinterpret_cast<float4*>(xs + k * 260 + c4 * 4) = xb4[i];
    }
    // stage q~[b] : 8 x 256 floats into padded rows
    const float4* qrow = reinterpret_cast<const float4*>(qt + (size_t)b * 2048);
    #pragma unroll
    for (int j = 0; j < 2; j++) {
        int i  = tid + j * 256;       // 0..511
        int h  = i >> 6;
        int d4 = i & 63;
        *reinterpret_cast<float4*>(qts + h * 260 + d4 * 4) = qrow[i];
    }
    __syncthreads();

    // ---- phase 1: warp w covers d in [w*32, w*32+32), lane = k, 8 head partials ----
    {
        int k = lane;
        float acc[8];
        #pragma unroll
        for (int h = 0; h < 8; h++) acc[h] = 0.0f;
        const float* xr = xs + k * 260 + w * 32;
        #pragma unroll
        for (int d4 = 0; d4 < 8; d4++) {
            float4 xv = *reinterpret_cast<const float4*>(xr + d4 * 4);
            #pragma unroll
            for (int h = 0; h < 8; h++) {
                float4 qv = *reinterpret_cast<const float4*>(qts + h * 260 + w * 32 + d4 * 4);
                acc[h] = fmaf(qv.x, xv.x, fmaf(qv.y, xv.y,
                          fmaf(qv.z, xv.z, fmaf(qv.w, xv.w, acc[h]))));
            }
        }
        #pragma unroll
        for (int h = 0; h < 8; h++)
            sred[w * 256 + h * 32 + k] = acc[h];
    }
    __syncthreads();

    // ---- softmax: warp w handles head h=w, lane = k ----
    {
        int h = w, k = lane;
        float sc = 0.0f;
        #pragma unroll
        for (int ww = 0; ww < 8; ww++)
            sc += sred[ww * 256 + h * 32 + k];
        sc *= 0.17677669529663687f;   // 1/sqrt(32)
        float m = sc;
        #pragma unroll
        for (int o = 16; o; o >>= 1) m = fmaxf(m, __shfl_xor_sync(0xFFFFFFFFu, m, o));
        float e = expf(sc - m);
        float s = e;
        #pragma unroll
        for (int o = 16; o; o >>= 1) s += __shfl_xor_sync(0xFFFFFFFFu, s, o);
        attns[h * 32 + k] = e / s;
    }
    __syncthreads();

    // ---- phase 2: ctx; warp = (4-head group, d-quarter), lane = d-pair ----
    {
        int hg  = w >> 2;
        int dqt = w & 3;
        int dbase = dqt * 64 + lane * 2;
        float acc[4][2];
        #pragma unroll
        for (int h = 0; h < 4; h++) { acc[h][0] = 0.f; acc[h][1] = 0.f; }
        #pragma unroll
        for (int k0 = 0; k0 < 32; k0 += 4) {
            float4 a0 = *reinterpret_cast<const float4*>(&attns[(hg * 4 + 0) * 32 + k0]);
            float4 a1 = *reinterpret_cast<const float4*>(&attns[(hg * 4 + 1) * 32 + k0]);
            float4 a2 = *reinterpret_cast<const float4*>(&attns[(hg * 4 + 2) * 32 + k0]);
            float4 a3 = *reinterpret_cast<const float4*>(&attns[(hg * 4 + 3) * 32 + k0]);
            float av0[4] = {a0.x, a0.y, a0.z, a0.w};
            float av1[4] = {a1.x, a1.y, a1.z, a1.w};
            float av2[4] = {a2.x, a2.y, a2.z, a2.w};
            float av3[4] = {a3.x, a3.y, a3.z, a3.w};
            #pragma unroll
            for (int kk = 0; kk < 4; kk++) {
                float2 xv = *reinterpret_cast<const float2*>(xs + (k0 + kk) * 260 + dbase);
                acc[0][0] = fmaf(av0[kk], xv.x, acc[0][0]);
                acc[0][1] = fmaf(av0[kk], xv.y, acc[0][1]);
                acc[1][0] = fmaf(av1[kk], xv.x, acc[1][0]);
                acc[1][1] = fmaf(av1[kk], xv.y, acc[1][1]);
                acc[2][0] = fmaf(av2[kk], xv.x, acc[2][0]);
                acc[2][1] = fmaf(av2[kk], xv.y, acc[2][1]);
                acc[3][0] = fmaf(av3[kk], xv.x, acc[3][0]);
                acc[3][1] = fmaf(av3[kk], xv.y, acc[3][1]);
            }
        }
        float* cb = ctx + (size_t)b * 2048;
        #pragma unroll
        for (int h = 0; h < 4; h++) {
            *reinterpret_cast<float2*>(cb + (hg * 4 + h) * 256 + dbase) =
                make_float2(acc[h][0], acc[h][1]);
        }
    }
}

// ---------------- out[b, h*32+j] = sum_d ctx[b,h,d] * W_v[d, h*32+j] ----------------
__global__ void vproj_kernel(const float* __restrict__ ctx, const float* __restrict__ Wv,
                             float* __restrict__ out) {
    __shared__ float Wvs[256 * 32];
    __shared__ float cs[16 * 256];
    int h  = blockIdx.y;
    int b0 = blockIdx.x * 16;
    int tid = threadIdx.x;
    for (int i = tid * 4; i < 8192; i += 1024) {
        int d = i >> 5, j = i & 31;
        *reinterpret_cast<float4*>(&Wvs[i]) =
            *reinterpret_cast<const float4*>(&Wv[d * 256 + h * 32 + j]);
    }
    for (int i = tid * 4; i < 4096; i += 1024) {
        int r = i >> 8, d2 = i & 255;
        *reinterpret_cast<float4*>(&cs[i]) =
            *reinterpret_cast<const float4*>(&ctx[(size_t)(b0 + r) * 2048 + h * 256 + d2]);
    }
    __syncthreads();
    int j  = tid & 31;
    int rg = tid >> 5;
    float acc0 = 0.0f, acc1 = 0.0f;
    #pragma unroll 4
    for (int d4 = 0; d4 < 64; d4++) {
        float w0 = Wvs[(d4 * 4 + 0) * 32 + j];
        float w1 = Wvs[(d4 * 4 + 1) * 32 + j];
        float w2 = Wvs[(d4 * 4 + 2) * 32 + j];
        float w3 = Wvs[(d4 * 4 + 3) * 32 + j];
        float4 c0 = *reinterpret_cast<const float4*>(&cs[rg * 256 + d4 * 4]);
        float4 c1 = *reinterpret_cast<const float4*>(&cs[(rg + 8) * 256 + d4 * 4]);
        acc0 += c0.x * w0 + c0.y * w1 + c0.z * w2 + c0.w * w3;
        acc1 += c1.x * w0 + c1.y * w1 + c1.z * w2 + c1.w * w3;
    }
    out[(size_t)(b0 + rg) * 256 + h * 32 + j]     = acc0;
    out[(size_t)(b0 + rg + 8) * 256 + h * 32 + j] = acc1;
}

// ---------------- launcher ----------------
extern "C" void kernel_launch(void* const* d_in, const int* in_sizes, int n_in,
                              void* d_out, int out_size) {
    const float* x_anc = (const float*)d_in[0];
    const float* x_nei = (const float*)d_in[1];
    const float* W_q   = (const float*)d_in[2];
    const float* W_k   = (const float*)d_in[3];
    const float* W_v   = (const float*)d_in[4];
    const float* W_o   = (const float*)d_in[5];
    const float* ln1_g = (const float*)d_in[6];
    const float* ln1_b = (const float*)d_in[7];
    const float* ln2_g = (const float*)d_in[8];
    const float* ln2_b = (const float*)d_in[9];
    const float* ff1_w = (const float*)d_in[10];
    const float* ff1_b = (const float*)d_in[11];
    const float* ff2_w = (const float*)d_in[12];
    const float* ff2_b = (const float*)d_in[13];
    float* out = (float*)d_out;

    float *p_lnx, *p_q, *p_qt, *p_ctx, *p_att, *p_x, *p_h, *p_ff;
    cudaGetSymbolAddress((void**)&p_lnx, g_lnx);
    cudaGetSymbolAddress((void**)&p_q,   g_q);
    cudaGetSymbolAddress((void**)&p_qt,  g_qt);
    cudaGetSymbolAddress((void**)&p_ctx, g_ctx);
    cudaGetSymbolAddress((void**)&p_att, g_att);
    cudaGetSymbolAddress((void**)&p_x,   g_x);
    cudaGetSymbolAddress((void**)&p_h,   g_h);
    cudaGetSymbolAddress((void**)&p_ff,  g_ff);

    dim3 lnBlock(32, 8);

    // 1. LN1
    ln_kernel<<<BN / 8, lnBlock>>>(x_anc, ln1_g, ln1_b, p_lnx);
    // 2. Q = LN1 @ W_q  (tf32 tensor cores)
    tgemm<0><<<dim3(DIM / 128, BN / 128), 256>>>(p_lnx, W_q, p_q, BN, DIM, DIM, nullptr, nullptr);
    // 3. q~ per head
    qtilde_kernel<<<dim3(BN / 8, NH), 256>>>(p_q, W_k, p_qt);
    // 4. attention core -> ctx
    attn_kernel<<<BN, 256>>>(x_nei, p_qt, p_ctx);
    // 5. out = ctx @ W_v (per head)
    vproj_kernel<<<dim3(BN / 16, NH), 256>>>(p_ctx, W_v, p_att);
    // 6. x = x_anc + att @ W_o
    tgemm<3><<<dim3(DIM / 128, BN / 128), 256>>>(p_att, W_o, p_x, BN, DIM, DIM, nullptr, x_anc);
    // 7. LN2
    ln_kernel<<<BN / 8, lnBlock>>>(p_x, ln2_g, ln2_b, p_h);
    // 8. ff = gelu(h @ ff1 + b1)
    tgemm<1><<<dim3(NFF / 128, BN / 128), 256>>>(p_h, ff1_w, p_ff, BN, NFF, DIM, ff1_b, nullptr);
    // 9. out = x + ff @ ff2 + b2
    tgemm<2><<<dim3(DIM / 128, BN / 128), 256>>>(p_ff, ff2_w, out, BN, DIM, NFF, ff2_b, p_x);
}

// round 6
// speedup vs baseline: 1.0989x; 1.0989x over previous
#include <cuda_runtime.h>
#include <math.h>
#include <stdint.h>

// Problem constants
#define BN  32768
#define DIM 256
#define NK  32
#define NH  8
#define NFF 1024
#define NDK 32

// ---------------- scratch (device globals: allocation-guard-safe) ----------------
__device__ __align__(128) float g_lnx[BN * DIM];        // LN1(x_anc)
__device__ __align__(128) float g_q[BN * DIM];          // Q
__device__ __align__(128) float g_qt[BN * NH * DIM];    // q~ [B, H, 256]
__device__ __align__(128) float g_ctx[BN * NH * DIM];   // ctx [B, H, 256]
__device__ __align__(128) float g_att[BN * DIM];        // attention output (pre-W_o)
__device__ __align__(128) float g_x[BN * DIM];          // x = x_anc + att @ W_o
__device__ __align__(128) float g_h[BN * DIM];          // LN2(x)
__device__ __align__(128) float g_ff[BN * NFF];         // gelu(h@ff1+b1)

// ---------------- LayerNorm: one warp per row ----------------
__global__ void ln_kernel(const float* __restrict__ x, const float* __restrict__ g,
                          const float* __restrict__ b, float* __restrict__ out) {
    int row  = blockIdx.x * 8 + threadIdx.y;
    int lane = threadIdx.x;
    const float4* xr = reinterpret_cast<const float4*>(x + (size_t)row * DIM);
    float4 v0 = xr[lane];
    float4 v1 = xr[lane + 32];
    float s  = v0.x + v0.y + v0.z + v0.w + v1.x + v1.y + v1.z + v1.w;
    float ss = v0.x*v0.x + v0.y*v0.y + v0.z*v0.z + v0.w*v0.w
             + v1.x*v1.x + v1.y*v1.y + v1.z*v1.z + v1.w*v1.w;
    #pragma unroll
    for (int o = 16; o; o >>= 1) {
        s  += __shfl_xor_sync(0xFFFFFFFFu, s,  o);
        ss += __shfl_xor_sync(0xFFFFFFFFu, ss, o);
    }
    float mu  = s * (1.0f / 256.0f);
    float var = ss * (1.0f / 256.0f) - mu * mu;
    float rs  = rsqrtf(var + 1e-5f);
    const float4* g4 = reinterpret_cast<const float4*>(g);
    const float4* b4 = reinterpret_cast<const float4*>(b);
    float4* orow = reinterpret_cast<float4*>(out + (size_t)row * DIM);
    #pragma unroll
    for (int p = 0; p < 2; p++) {
        int idx = lane + p * 32;
        float4 v = (p == 0) ? v0 : v1;
        float4 gg = g4[idx], bb = b4[idx];
        float4 o4;
        o4.x = (v.x - mu) * rs * gg.x + bb.x;
        o4.y = (v.y - mu) * rs * gg.y + bb.y;
        o4.z = (v.z - mu) * rs * gg.z + bb.z;
        o4.w = (v.w - mu) * rs * gg.w + bb.w;
        orow[idx] = o4;
    }
}

__device__ __forceinline__ float gelu_exact(float v) {
    return 0.5f * v * (1.0f + erff(v * 0.70710678118654752f));
}

// ---------------- tf32 tensor-core GEMM: 128x128x16, A k-pair-interleaved ----------------
// MODE 0: C = A@B
// MODE 1: C = gelu(A@B + bias)
// MODE 2: C = A@B + bias + resid
// MODE 3: C = A@B + resid
__device__ __forceinline__ void mma_tf32(float c[4], const uint32_t a[4], const uint32_t b[2]) {
    asm volatile(
        "mma.sync.aligned.m16n8k8.row.col.f32.tf32.tf32.f32 "
        "{%0,%1,%2,%3}, {%4,%5,%6,%7}, {%8,%9}, {%0,%1,%2,%3};\n"
        : "+f"(c[0]), "+f"(c[1]), "+f"(c[2]), "+f"(c[3])
        : "r"(a[0]), "r"(a[1]), "r"(a[2]), "r"(a[3]), "r"(b[0]), "r"(b[1]));
}

template <int MODE>
__global__ __launch_bounds__(256, 2)
void tgemm(const float* __restrict__ A, const float* __restrict__ Bw,
           float* __restrict__ C, int M, int N, int Kd,
           const float* __restrict__ bias, const float* __restrict__ resid) {
    // As: k-pair-interleaved. Float offset (ks + 2*fc) within a row holds the
    // pair (k = ks+fc, k = ks+fc+4). Stride 24 floats (12 pairs): frag LDS.64
    // pair-address = r*12 + ks/2 + fc -> conflict-free per half-warp phase.
    __shared__ float As[2][128][24];
    __shared__ float Bs[2][16][136];

    const int tid  = threadIdx.x;
    const int lane = tid & 31;
    const int wid  = tid >> 5;
    const int m0 = blockIdx.y * 128;
    const int n0 = blockIdx.x * 128;
    const int warp_m = (wid & 1) * 64;
    const int warp_n = (wid >> 1) * 32;

    // global-load assignments
    const int aRow = tid >> 1;            // 0..127
    const int aCol = (tid & 1) * 8;       // 0 or 8 (float offset of the pair region)
    const int bRow = tid >> 4;            // 0..15
    const int bCol = (tid & 15) * 4;      // 0..60

    const float* Ag = A  + (size_t)(m0 + aRow) * Kd + aCol;
    const float* Bg = Bw + (size_t)bRow * N + n0 + bCol;

    float c[4][4][4];
    #pragma unroll
    for (int mt = 0; mt < 4; mt++)
        #pragma unroll
        for (int nt = 0; nt < 4; nt++)
            #pragma unroll
            for (int i = 0; i < 4; i++) c[mt][nt][i] = 0.0f;

    // prologue: load k-tile 0 into buffer 0
    float4 a0 = *reinterpret_cast<const float4*>(Ag);       // k = aCol..aCol+3
    float4 a1 = *reinterpret_cast<const float4*>(Ag + 4);   // k = aCol+4..aCol+7
    float4 b0 = *reinterpret_cast<const float4*>(Bg);
    float4 b1 = *reinterpret_cast<const float4*>(Bg + 64);
    {
        float* Ad = &As[0][aRow][aCol];
        *reinterpret_cast<float2*>(Ad + 0) = make_float2(a0.x, a1.x);
        *reinterpret_cast<float2*>(Ad + 2) = make_float2(a0.y, a1.y);
        *reinterpret_cast<float2*>(Ad + 4) = make_float2(a0.z, a1.z);
        *reinterpret_cast<float2*>(Ad + 6) = make_float2(a0.w, a1.w);
    }
    *reinterpret_cast<float4*>(&Bs[0][bRow][bCol])      = b0;
    *reinterpret_cast<float4*>(&Bs[0][bRow][bCol + 64]) = b1;
    __syncthreads();

    const int KT = Kd >> 4;
    int buf = 0;
    const int fr = lane >> 2;     // 0..7
    const int fc = lane & 3;      // 0..3

    for (int kt = 0; kt < KT; kt++) {
        if (kt + 1 < KT) {
            const float* Ap = Ag + (kt + 1) * 16;
            const float* Bp = Bg + (size_t)(kt + 1) * 16 * N;
            a0 = *reinterpret_cast<const float4*>(Ap);
            a1 = *reinterpret_cast<const float4*>(Ap + 4);
            b0 = *reinterpret_cast<const float4*>(Bp);
            b1 = *reinterpret_cast<const float4*>(Bp + 64);
        }
        #pragma unroll
        for (int ks = 0; ks < 16; ks += 8) {
            uint32_t af[4][4];
            uint32_t bf[4][2];
            #pragma unroll
            for (int mt = 0; mt < 4; mt++) {
                int r = warp_m + mt * 16 + fr;
                float2 pa = *reinterpret_cast<const float2*>(&As[buf][r][ks + 2 * fc]);
                float2 pb = *reinterpret_cast<const float2*>(&As[buf][r + 8][ks + 2 * fc]);
                af[mt][0] = __float_as_uint(pa.x);   // k = ks+fc,   row r
                af[mt][1] = __float_as_uint(pb.x);   // k = ks+fc,   row r+8
                af[mt][2] = __float_as_uint(pa.y);   // k = ks+fc+4, row r
                af[mt][3] = __float_as_uint(pb.y);   // k = ks+fc+4, row r+8
            }
            #pragma unroll
            for (int nt = 0; nt < 4; nt++) {
                int cn = warp_n + nt * 8 + fr;
                bf[nt][0] = __float_as_uint(Bs[buf][ks + fc][cn]);
                bf[nt][1] = __float_as_uint(Bs[buf][ks + 4 + fc][cn]);
            }
            #pragma unroll
            for (int mt = 0; mt < 4; mt++)
                #pragma unroll
                for (int nt = 0; nt < 4; nt++)
                    mma_tf32(c[mt][nt], af[mt], bf[nt]);
        }
        if (kt + 1 < KT) {
            buf ^= 1;
            float* Ad = &As[buf][aRow][aCol];
            *reinterpret_cast<float2*>(Ad + 0) = make_float2(a0.x, a1.x);
            *reinterpret_cast<float2*>(Ad + 2) = make_float2(a0.y, a1.y);
            *reinterpret_cast<float2*>(Ad + 4) = make_float2(a0.z, a1.z);
            *reinterpret_cast<float2*>(Ad + 6) = make_float2(a0.w, a1.w);
            *reinterpret_cast<float4*>(&Bs[buf][bRow][bCol])      = b0;
            *reinterpret_cast<float4*>(&Bs[buf][bRow][bCol + 64]) = b1;
        }
        __syncthreads();
    }

    // epilogue
    #pragma unroll
    for (int mt = 0; mt < 4; mt++) {
        #pragma unroll
        for (int nt = 0; nt < 4; nt++) {
            int row0 = m0 + warp_m + mt * 16 + fr;
            int col  = n0 + warp_n + nt * 8 + fc * 2;
            float v0 = c[mt][nt][0], v1 = c[mt][nt][1];
            float v2 = c[mt][nt][2], v3 = c[mt][nt][3];
            if (MODE == 1 || MODE == 2) {
                float2 bv = *reinterpret_cast<const float2*>(bias + col);
                v0 += bv.x; v1 += bv.y; v2 += bv.x; v3 += bv.y;
            }
            if (MODE == 1) {
                v0 = gelu_exact(v0); v1 = gelu_exact(v1);
                v2 = gelu_exact(v2); v3 = gelu_exact(v3);
            }
            if (MODE == 2 || MODE == 3) {
                float2 r0 = *reinterpret_cast<const float2*>(resid + (size_t)row0 * N + col);
                float2 r1 = *reinterpret_cast<const float2*>(resid + (size_t)(row0 + 8) * N + col);
                v0 += r0.x; v1 += r0.y; v2 += r1.x; v3 += r1.y;
            }
            float2 o0 = make_float2(v0, v1);
            float2 o1 = make_float2(v2, v3);
            *reinterpret_cast<float2*>(C + (size_t)row0 * N + col)       = o0;
            *reinterpret_cast<float2*>(C + (size_t)(row0 + 8) * N + col) = o1;
        }
    }
}

// ---------------- q~[b,h,d] = sum_j Q[b, h*32+j] * W_k[d, h*32+j] ----------------
// 32 anchors per block: amortize the 32KB W_k slice over 4x more work.
__global__ void qtilde_kernel(const float* __restrict__ Q, const float* __restrict__ Wk,
                              float* __restrict__ qt) {
    __shared__ float Wks[256 * 33];
    __shared__ float Qs[32 * 32];
    int h  = blockIdx.y;
    int b0 = blockIdx.x * 32;
    int tid = threadIdx.x;
    for (int i = tid; i < 8192; i += 256) {
        int d = i >> 5, j = i & 31;
        Wks[d * 33 + j] = Wk[d * 256 + h * 32 + j];
    }
    #pragma unroll
    for (int p = 0; p < 4; p++) {
        int i = tid + p * 256;
        int r = i >> 5, j = i & 31;
        Qs[i] = Q[(size_t)(b0 + r) * 256 + h * 32 + j];
    }
    __syncthreads();
    int d = tid;
    float w[32];
    #pragma unroll
    for (int j = 0; j < 32; j++) w[j] = Wks[d * 33 + j];
    const float4* Qs4 = reinterpret_cast<const float4*>(Qs);
    // process anchors in two halves of 16 to bound register pressure
    #pragma unroll
    for (int half = 0; half < 2; half++) {
        float acc[16];
        #pragma unroll
        for (int r = 0; r < 16; r++) acc[r] = 0.0f;
        #pragma unroll
        for (int r = 0; r < 16; r++) {
            int rr = half * 16 + r;
            #pragma unroll
            for (int j4 = 0; j4 < 8; j4++) {
                float4 q = Qs4[rr * 8 + j4];
                acc[r] += q.x * w[j4 * 4 + 0] + q.y * w[j4 * 4 + 1]
                        + q.z * w[j4 * 4 + 2] + q.w * w[j4 * 4 + 3];
            }
        }
        #pragma unroll
        for (int r = 0; r < 16; r++)
            qt[(size_t)(b0 + half * 16 + r) * 2048 + h * 256 + d] = acc[r];
    }
}

// ---------------- attention core (R4 version), one block per anchor b ----------------
// Phase1: warp = d-eighth x all 8 heads (x float4 feeds 8 dot chains; q smem broadcast).
// Phase2: warp = (4-head group, d-quarter); x float2 feeds 4 heads.
__global__ __launch_bounds__(256)
void attn_kernel(const float* __restrict__ xnei, const float* __restrict__ qt,
                 float* __restrict__ ctx) {
    __shared__ float xs[32 * 260];   // stride 260: conflict-free float4/float2 row access
    __shared__ float qts[8 * 260];   // stride 260: conflict-free broadcasts
    __shared__ float sred[8 * 256];  // [w-slice][h*32+k]
    __shared__ float attns[8 * 32];
    int b    = blockIdx.x;
    int tid  = threadIdx.x;
    int lane = tid & 31;
    int w    = tid >> 5;

    // stage x_nei[b] : 32 x 256 floats
    const float4* xb4 = reinterpret_cast<const float4*>(xnei + (size_t)b * 8192);
    #pragma unroll
    for (int j = 0; j < 8; j++) {
        int i  = tid + j * 256;
        int k  = i >> 6;
        int c4 = i & 63;
        *reinterpret_cast<float4*>(xs + k * 260 + c4 * 4) = xb4[i];
    }
    // stage q~[b] : 8 x 256 floats into padded rows
    const float4* qrow = reinterpret_cast<const float4*>(qt + (size_t)b * 2048);
    #pragma unroll
    for (int j = 0; j < 2; j++) {
        int i  = tid + j * 256;       // 0..511
        int h  = i >> 6;
        int d4 = i & 63;
        *reinterpret_cast<float4*>(qts + h * 260 + d4 * 4) = qrow[i];
    }
    __syncthreads();

    // ---- phase 1: warp w covers d in [w*32, w*32+32), lane = k, 8 head partials ----
    {
        int k = lane;
        float acc[8];
        #pragma unroll
        for (int h = 0; h < 8; h++) acc[h] = 0.0f;
        const float* xr = xs + k * 260 + w * 32;
        #pragma unroll
        for (int d4 = 0; d4 < 8; d4++) {
            float4 xv = *reinterpret_cast<const float4*>(xr + d4 * 4);
            #pragma unroll
            for (int h = 0; h < 8; h++) {
                float4 qv = *reinterpret_cast<const float4*>(qts + h * 260 + w * 32 + d4 * 4);
                acc[h] = fmaf(qv.x, xv.x, fmaf(qv.y, xv.y,
                          fmaf(qv.z, xv.z, fmaf(qv.w, xv.w, acc[h]))));
            }
        }
        #pragma unroll
        for (int h = 0; h < 8; h++)
            sred[w * 256 + h * 32 + k] = acc[h];
    }
    __syncthreads();

    // ---- softmax: warp w handles head h=w, lane = k ----
    {
        int h = w, k = lane;
        float sc = 0.0f;
        #pragma unroll
        for (int ww = 0; ww < 8; ww++)
            sc += sred[ww * 256 + h * 32 + k];
        sc *= 0.17677669529663687f;   // 1/sqrt(32)
        float m = sc;
        #pragma unroll
        for (int o = 16; o; o >>= 1) m = fmaxf(m, __shfl_xor_sync(0xFFFFFFFFu, m, o));
        float e = expf(sc - m);
        float s = e;
        #pragma unroll
        for (int o = 16; o; o >>= 1) s += __shfl_xor_sync(0xFFFFFFFFu, s, o);
        attns[h * 32 + k] = e / s;
    }
    __syncthreads();

    // ---- phase 2: ctx; warp = (4-head group, d-quarter), lane = d-pair ----
    {
        int hg  = w >> 2;
        int dqt = w & 3;
        int dbase = dqt * 64 + lane * 2;
        float acc[4][2];
        #pragma unroll
        for (int h = 0; h < 4; h++) { acc[h][0] = 0.f; acc[h][1] = 0.f; }
        #pragma unroll
        for (int k0 = 0; k0 < 32; k0 += 4) {
            float4 a0 = *reinterpret_cast<const float4*>(&attns[(hg * 4 + 0) * 32 + k0]);
            float4 a1 = *reinterpret_cast<const float4*>(&attns[(hg * 4 + 1) * 32 + k0]);
            float4 a2 = *reinterpret_cast<const float4*>(&attns[(hg * 4 + 2) * 32 + k0]);
            float4 a3 = *reinterpret_cast<const float4*>(&attns[(hg * 4 + 3) * 32 + k0]);
            float av0[4] = {a0.x, a0.y, a0.z, a0.w};
            float av1[4] = {a1.x, a1.y, a1.z, a1.w};
            float av2[4] = {a2.x, a2.y, a2.z, a2.w};
            float av3[4] = {a3.x, a3.y, a3.z, a3.w};
            #pragma unroll
            for (int kk = 0; kk < 4; kk++) {
                float2 xv = *reinterpret_cast<const float2*>(xs + (k0 + kk) * 260 + dbase);
                acc[0][0] = fmaf(av0[kk], xv.x, acc[0][0]);
                acc[0][1] = fmaf(av0[kk], xv.y, acc[0][1]);
                acc[1][0] = fmaf(av1[kk], xv.x, acc[1][0]);
                acc[1][1] = fmaf(av1[kk], xv.y, acc[1][1]);
                acc[2][0] = fmaf(av2[kk], xv.x, acc[2][0]);
                acc[2][1] = fmaf(av2[kk], xv.y, acc[2][1]);
                acc[3][0] = fmaf(av3[kk], xv.x, acc[3][0]);
                acc[3][1] = fmaf(av3[kk], xv.y, acc[3][1]);
            }
        }
        float* cb = ctx + (size_t)b * 2048;
        #pragma unroll
        for (int h = 0; h < 4; h++) {
            *reinterpret_cast<float2*>(cb + (hg * 4 + h) * 256 + dbase) =
                make_float2(acc[h][0], acc[h][1]);
        }
    }
}

// ---------------- out[b, h*32+j] = sum_d ctx[b,h,d] * W_v[d, h*32+j] ----------------
// 32 anchors per block (dynamic smem: Wvs 32KB + cs 32KB).
#define VPROJ_SMEM (16384 * 4)
__global__ void vproj_kernel(const float* __restrict__ ctx, const float* __restrict__ Wv,
                             float* __restrict__ out) {
    extern __shared__ float vsm[];
    float* Wvs = vsm;          // [256][32]
    float* cs  = vsm + 8192;   // [32][256]
    int h  = blockIdx.y;
    int b0 = blockIdx.x * 32;
    int tid = threadIdx.x;
    for (int i = tid * 4; i < 8192; i += 1024) {
        int d = i >> 5, j = i & 31;
        *reinterpret_cast<float4*>(&Wvs[i]) =
            *reinterpret_cast<const float4*>(&Wv[d * 256 + h * 32 + j]);
    }
    for (int i = tid * 4; i < 8192; i += 1024) {
        int r = i >> 8, d2 = i & 255;
        *reinterpret_cast<float4*>(&cs[i]) =
            *reinterpret_cast<const float4*>(&ctx[(size_t)(b0 + r) * 2048 + h * 256 + d2]);
    }
    __syncthreads();
    int j  = tid & 31;
    int rg = tid >> 5;    // 0..7, handles rows rg, rg+8, rg+16, rg+24
    float acc0 = 0.0f, acc1 = 0.0f, acc2 = 0.0f, acc3 = 0.0f;
    #pragma unroll 4
    for (int d4 = 0; d4 < 64; d4++) {
        float w0 = Wvs[(d4 * 4 + 0) * 32 + j];
        float w1 = Wvs[(d4 * 4 + 1) * 32 + j];
        float w2 = Wvs[(d4 * 4 + 2) * 32 + j];
        float w3 = Wvs[(d4 * 4 + 3) * 32 + j];
        float4 c0 = *reinterpret_cast<const float4*>(&cs[(rg +  0) * 256 + d4 * 4]);
        float4 c1 = *reinterpret_cast<const float4*>(&cs[(rg +  8) * 256 + d4 * 4]);
        float4 c2 = *reinterpret_cast<const float4*>(&cs[(rg + 16) * 256 + d4 * 4]);
        float4 c3 = *reinterpret_cast<const float4*>(&cs[(rg + 24) * 256 + d4 * 4]);
        acc0 += c0.x * w0 + c0.y * w1 + c0.z * w2 + c0.w * w3;
        acc1 += c1.x * w0 + c1.y * w1 + c1.z * w2 + c1.w * w3;
        acc2 += c2.x * w0 + c2.y * w1 + c2.z * w2 + c2.w * w3;
        acc3 += c3.x * w0 + c3.y * w1 + c3.z * w2 + c3.w * w3;
    }
    out[(size_t)(b0 + rg +  0) * 256 + h * 32 + j] = acc0;
    out[(size_t)(b0 + rg +  8) * 256 + h * 32 + j] = acc1;
    out[(size_t)(b0 + rg + 16) * 256 + h * 32 + j] = acc2;
    out[(size_t)(b0 + rg + 24) * 256 + h * 32 + j] = acc3;
}

// ---------------- launcher ----------------
extern "C" void kernel_launch(void* const* d_in, const int* in_sizes, int n_in,
                              void* d_out, int out_size) {
    const float* x_anc = (const float*)d_in[0];
    const float* x_nei = (const float*)d_in[1];
    const float* W_q   = (const float*)d_in[2];
    const float* W_k   = (const float*)d_in[3];
    const float* W_v   = (const float*)d_in[4];
    const float* W_o   = (const float*)d_in[5];
    const float* ln1_g = (const float*)d_in[6];
    const float* ln1_b = (const float*)d_in[7];
    const float* ln2_g = (const float*)d_in[8];
    const float* ln2_b = (const float*)d_in[9];
    const float* ff1_w = (const float*)d_in[10];
    const float* ff1_b = (const float*)d_in[11];
    const float* ff2_w = (const float*)d_in[12];
    const float* ff2_b = (const float*)d_in[13];
    float* out = (float*)d_out;

    float *p_lnx, *p_q, *p_qt, *p_ctx, *p_att, *p_x, *p_h, *p_ff;
    cudaGetSymbolAddress((void**)&p_lnx, g_lnx);
    cudaGetSymbolAddress((void**)&p_q,   g_q);
    cudaGetSymbolAddress((void**)&p_qt,  g_qt);
    cudaGetSymbolAddress((void**)&p_ctx, g_ctx);
    cudaGetSymbolAddress((void**)&p_att, g_att);
    cudaGetSymbolAddress((void**)&p_x,   g_x);
    cudaGetSymbolAddress((void**)&p_h,   g_h);
    cudaGetSymbolAddress((void**)&p_ff,  g_ff);

    cudaFuncSetAttribute(vproj_kernel, cudaFuncAttributeMaxDynamicSharedMemorySize, VPROJ_SMEM);

    dim3 lnBlock(32, 8);

    // 1. LN1
    ln_kernel<<<BN / 8, lnBlock>>>(x_anc, ln1_g, ln1_b, p_lnx);
    // 2. Q = LN1 @ W_q  (tf32 tensor cores)
    tgemm<0><<<dim3(DIM / 128, BN / 128), 256>>>(p_lnx, W_q, p_q, BN, DIM, DIM, nullptr, nullptr);
    // 3. q~ per head (32 anchors/block)
    qtilde_kernel<<<dim3(BN / 32, NH), 256>>>(p_q, W_k, p_qt);
    // 4. attention core -> ctx
    attn_kernel<<<BN, 256>>>(x_nei, p_qt, p_ctx);
    // 5. out = ctx @ W_v (per head, 32 anchors/block)
    vproj_kernel<<<dim3(BN / 32, NH), 256, VPROJ_SMEM>>>(p_ctx, W_v, p_att);
    // 6. x = x_anc + att @ W_o
    tgemm<3><<<dim3(DIM / 128, BN / 128), 256>>>(p_att, W_o, p_x, BN, DIM, DIM, nullptr, x_anc);
    // 7. LN2
    ln_kernel<<<BN / 8, lnBlock>>>(p_x, ln2_g, ln2_b, p_h);
    // 8. ff = gelu(h @ ff1 + b1)
    tgemm<1><<<dim3(NFF / 128, BN / 128), 256>>>(p_h, ff1_w, p_ff, BN, NFF, DIM, ff1_b, nullptr);
    // 9. out = x + ff @ ff2 + b2
    tgemm<2><<<dim3(DIM / 128, BN / 128), 256>>>(p_ff, ff2_w, out, BN, DIM, NFF, ff2_b, p_x);
}

// round 8
// speedup vs baseline: 1.2413x; 1.1296x over previous
#include <cuda_runtime.h>
#include <cuda_fp16.h>
#include <math.h>
#include <stdint.h>

// Problem constants
#define BN  32768
#define DIM 256
#define NK  32
#define NH  8
#define NFF 1024
#define NDK 32

// ---------------- scratch (device globals: allocation-guard-safe) ----------------
__device__ __align__(128) __half g_lnx[BN * DIM];       // LN1(x_anc), half
__device__ __align__(128) float  g_q[BN * DIM];         // Q (fp32, feeds qtilde)
__device__ __align__(128) float  g_qt[BN * NH * DIM];   // q~ [B, H, 256]
__device__ __align__(128) float  g_ctx[BN * NH * DIM];  // ctx [B, H, 256]
__device__ __align__(128) __half g_att[BN * DIM];       // attention out (pre-W_o), half
__device__ __align__(128) float  g_x[BN * DIM];         // x = x_anc + att @ W_o
__device__ __align__(128) __half g_h[BN * DIM];         // LN2(x), half
__device__ __align__(128) __half g_ff[BN * NFF];        // gelu(h@ff1+b1), half
// transposed half weights: [n][k] rows
__device__ __align__(128) __half g_wtq[DIM * DIM];
__device__ __align__(128) __half g_wto[DIM * DIM];
__device__ __align__(128) __half g_wt1[DIM * NFF];
__device__ __align__(128) __half g_wt2[NFF * DIM];

// ---------------- LayerNorm: one warp per row, half output ----------------
__global__ void ln_kernel(const float* __restrict__ x, const float* __restrict__ g,
                          const float* __restrict__ b, __half* __restrict__ out) {
    int row  = blockIdx.x * 8 + threadIdx.y;
    int lane = threadIdx.x;
    const float4* xr = reinterpret_cast<const float4*>(x + (size_t)row * DIM);
    float4 v0 = xr[lane];
    float4 v1 = xr[lane + 32];
    float s  = v0.x + v0.y + v0.z + v0.w + v1.x + v1.y + v1.z + v1.w;
    float ss = v0.x*v0.x + v0.y*v0.y + v0.z*v0.z + v0.w*v0.w
             + v1.x*v1.x + v1.y*v1.y + v1.z*v1.z + v1.w*v1.w;
    #pragma unroll
    for (int o = 16; o; o >>= 1) {
        s  += __shfl_xor_sync(0xFFFFFFFFu, s,  o);
        ss += __shfl_xor_sync(0xFFFFFFFFu, ss, o);
    }
    float mu  = s * (1.0f / 256.0f);
    float var = ss * (1.0f / 256.0f) - mu * mu;
    float rs  = rsqrtf(var + 1e-5f);
    const float4* g4 = reinterpret_cast<const float4*>(g);
    const float4* b4 = reinterpret_cast<const float4*>(b);
    __half* orow = out + (size_t)row * DIM;
    #pragma unroll
    for (int p = 0; p < 2; p++) {
        int idx = lane + p * 32;
        float4 v = (p == 0) ? v0 : v1;
        float4 gg = g4[idx], bb = b4[idx];
        float o0 = (v.x - mu) * rs * gg.x + bb.x;
        float o1 = (v.y - mu) * rs * gg.y + bb.y;
        float o2 = (v.z - mu) * rs * gg.z + bb.z;
        float o3 = (v.w - mu) * rs * gg.w + bb.w;
        __half2 ha = __floats2half2_rn(o0, o1);
        __half2 hb = __floats2half2_rn(o2, o3);
        uint2 u;
        u.x = *reinterpret_cast<uint32_t*>(&ha);
        u.y = *reinterpret_cast<uint32_t*>(&hb);
        *reinterpret_cast<uint2*>(orow + idx * 4) = u;
    }
}

__device__ __forceinline__ float gelu_exact(float v) {
    return 0.5f * v * (1.0f + erff(v * 0.70710678118654752f));
}

// ---------------- weight transpose+convert: out[C][R] = (half)in[R][C] ----------------
__global__ void transpose_kernel(const float* __restrict__ in, __half* __restrict__ out,
                                 int R, int C) {
    __shared__ float t[32][33];
    int c0 = blockIdx.x * 32, r0 = blockIdx.y * 32;
    int tx = threadIdx.x, ty = threadIdx.y;   // (32, 8)
    #pragma unroll
    for (int j = 0; j < 4; j++)
        t[ty + j * 8][tx] = in[(size_t)(r0 + ty + j * 8) * C + c0 + tx];
    __syncthreads();
    #pragma unroll
    for (int j = 0; j < 4; j++)
        out[(size_t)(c0 + ty + j * 8) * R + r0 + tx] = __float2half_rn(t[tx][ty + j * 8]);
}

// ================= fp16 tensor-core GEMM: 128x128 tile, m16n8k16 + ldmatrix =================
// A [m][k] half, BT = W^T [n][k] half. C = A @ B. K chunked by 32.
// smem rows padded to 40 halves (80B): ldmatrix row-addresses conflict-free.
__device__ __forceinline__ uint32_t smem_u32(const void* p) {
    uint32_t a;
    asm("{ .reg .u64 t; cvta.to.shared.u64 t, %1; cvt.u32.u64 %0, t; }" : "=r"(a) : "l"(p));
    return a;
}
__device__ __forceinline__ void ldsm_x4(uint32_t r[4], uint32_t addr) {
    asm volatile("ldmatrix.sync.aligned.m8n8.x4.shared.b16 {%0,%1,%2,%3}, [%4];"
                 : "=r"(r[0]), "=r"(r[1]), "=r"(r[2]), "=r"(r[3]) : "r"(addr));
}
__device__ __forceinline__ void mma_f16(float c[4], const uint32_t a[4],
                                        uint32_t b0, uint32_t b1) {
    asm volatile(
        "mma.sync.aligned.m16n8k16.row.col.f32.f16.f16.f32 "
        "{%0,%1,%2,%3}, {%4,%5,%6,%7}, {%8,%9}, {%0,%1,%2,%3};\n"
        : "+f"(c[0]), "+f"(c[1]), "+f"(c[2]), "+f"(c[3])
        : "r"(a[0]), "r"(a[1]), "r"(a[2]), "r"(a[3]), "r"(b0), "r"(b1));
}

#define HS 40                     // halves per smem row
#define HBUF (128 * HS * 2)       // bytes per buffer

// MODE 0: C=A@B (f32)   1: gelu(A@B+bias) (HALF out)   2: A@B+bias+resid (f32)   3: A@B+resid (f32)
template <int MODE>
__global__ __launch_bounds__(256, 2)
void hgemm(const __half* __restrict__ A, const __half* __restrict__ BT,
           void* __restrict__ Cout, int M, int N, int Kd,
           const float* __restrict__ bias, const float* __restrict__ resid) {
    __shared__ __half As[2][128][HS];
    __shared__ __half Bs[2][128][HS];

    const int tid  = threadIdx.x;
    const int lane = tid & 31;
    const int wid  = tid >> 5;
    const int m0 = blockIdx.y * 128;
    const int n0 = blockIdx.x * 128;
    const int warp_m = (wid & 1) * 64;
    const int warp_n = (wid >> 1) * 32;

    // tile loaders: thread -> row tid>>1, half-col (tid&1)*16 (16 halves = 2 x uint4)
    const int ldRow = tid >> 1;
    const int ldCol = (tid & 1) * 16;
    const __half* Ag = A  + (size_t)(m0 + ldRow) * Kd + ldCol;
    const __half* Bg = BT + (size_t)(n0 + ldRow) * Kd + ldCol;

    float c[4][4][4];
    #pragma unroll
    for (int mt = 0; mt < 4; mt++)
        #pragma unroll
        for (int nt = 0; nt < 4; nt++)
            #pragma unroll
            for (int i = 0; i < 4; i++) c[mt][nt][i] = 0.0f;

    // ldmatrix per-lane addresses
    const uint32_t as_base = smem_u32(&As[0][0][0]);
    const uint32_t bs_base = smem_u32(&Bs[0][0][0]);
    const int a_row = warp_m + (lane & 7) + ((lane >> 3) & 1) * 8;
    const int a_k   = (lane >> 4) * 8;
    const int b_row = warp_n + (lane & 7) + ((lane >> 4) & 1) * 8;
    const int b_k   = ((lane >> 3) & 1) * 8;
    const uint32_t aAddr0 = as_base + (uint32_t)(a_row * HS + a_k) * 2;
    const uint32_t bAddr0 = bs_base + (uint32_t)(b_row * HS + b_k) * 2;

    // prologue: chunk 0 -> buf 0
    uint4 av0 = *reinterpret_cast<const uint4*>(Ag);
    uint4 av1 = *reinterpret_cast<const uint4*>(Ag + 8);
    uint4 bv0 = *reinterpret_cast<const uint4*>(Bg);
    uint4 bv1 = *reinterpret_cast<const uint4*>(Bg + 8);
    *reinterpret_cast<uint4*>(&As[0][ldRow][ldCol])     = av0;
    *reinterpret_cast<uint4*>(&As[0][ldRow][ldCol + 8]) = av1;
    *reinterpret_cast<uint4*>(&Bs[0][ldRow][ldCol])     = bv0;
    *reinterpret_cast<uint4*>(&Bs[0][ldRow][ldCol + 8]) = bv1;
    __syncthreads();

    const int KT = Kd >> 5;   // k32 chunks
    int buf = 0;
    for (int kt = 0; kt < KT; kt++) {
        if (kt + 1 < KT) {
            const __half* Ap = Ag + (kt + 1) * 32;
            const __half* Bp = Bg + (kt + 1) * 32;
            av0 = *reinterpret_cast<const uint4*>(Ap);
            av1 = *reinterpret_cast<const uint4*>(Ap + 8);
            bv0 = *reinterpret_cast<const uint4*>(Bp);
            bv1 = *reinterpret_cast<const uint4*>(Bp + 8);
        }
        const uint32_t bo = (uint32_t)buf * HBUF;
        #pragma unroll
        for (int ks = 0; ks < 2; ks++) {          // two k16 steps in the k32 chunk
            uint32_t af[4][4];
            uint32_t bf[2][4];
            #pragma unroll
            for (int mt = 0; mt < 4; mt++)
                ldsm_x4(af[mt], aAddr0 + bo + (uint32_t)(mt * 16 * HS + ks * 16) * 2);
            #pragma unroll
            for (int ntp = 0; ntp < 2; ntp++)
                ldsm_x4(bf[ntp], bAddr0 + bo + (uint32_t)(ntp * 16 * HS + ks * 16) * 2);
            #pragma unroll
            for (int mt = 0; mt < 4; mt++) {
                #pragma unroll
                for (int nt = 0; nt < 4; nt++) {
                    uint32_t b0 = (nt & 1) ? bf[nt >> 1][2] : bf[nt >> 1][0];
                    uint32_t b1 = (nt & 1) ? bf[nt >> 1][3] : bf[nt >> 1][1];
                    mma_f16(c[mt][nt], af[mt], b0, b1);
                }
            }
        }
        if (kt + 1 < KT) {
            buf ^= 1;
            *reinterpret_cast<uint4*>(&As[buf][ldRow][ldCol])     = av0;
            *reinterpret_cast<uint4*>(&As[buf][ldRow][ldCol + 8]) = av1;
            *reinterpret_cast<uint4*>(&Bs[buf][ldRow][ldCol])     = bv0;
            *reinterpret_cast<uint4*>(&Bs[buf][ldRow][ldCol + 8]) = bv1;
        }
        __syncthreads();
    }

    // epilogue
    const int fr = lane >> 2;
    const int fc = lane & 3;
    #pragma unroll
    for (int mt = 0; mt < 4; mt++) {
        #pragma unroll
        for (int nt = 0; nt < 4; nt++) {
            int row0 = m0 + warp_m + mt * 16 + fr;
            int col  = n0 + warp_n + nt * 8 + fc * 2;
            float v0 = c[mt][nt][0], v1 = c[mt][nt][1];
            float v2 = c[mt][nt][2], v3 = c[mt][nt][3];
            if (MODE == 1 || MODE == 2) {
                float2 bv = *reinterpret_cast<const float2*>(bias + col);
                v0 += bv.x; v1 += bv.y; v2 += bv.x; v3 += bv.y;
            }
            if (MODE == 1) {
                v0 = gelu_exact(v0); v1 = gelu_exact(v1);
                v2 = gelu_exact(v2); v3 = gelu_exact(v3);
            }
            if (MODE == 2 || MODE == 3) {
                float2 r0 = *reinterpret_cast<const float2*>(resid + (size_t)row0 * N + col);
                float2 r1 = *reinterpret_cast<const float2*>(resid + (size_t)(row0 + 8) * N + col);
                v0 += r0.x; v1 += r0.y; v2 += r1.x; v3 += r1.y;
            }
            if (MODE == 1) {
                __half* Ch = reinterpret_cast<__half*>(Cout);
                __half2 h0 = __floats2half2_rn(v0, v1);
                __half2 h1 = __floats2half2_rn(v2, v3);
                *reinterpret_cast<__half2*>(Ch + (size_t)row0 * N + col)       = h0;
                *reinterpret_cast<__half2*>(Ch + (size_t)(row0 + 8) * N + col) = h1;
            } else {
                float* Cf = reinterpret_cast<float*>(Cout);
                *reinterpret_cast<float2*>(Cf + (size_t)row0 * N + col)       = make_float2(v0, v1);
                *reinterpret_cast<float2*>(Cf + (size_t)(row0 + 8) * N + col) = make_float2(v2, v3);
            }
        }
    }
}

// ---------------- q~[b,h,d] = sum_j Q[b, h*32+j] * W_k[d, h*32+j] ----------------
__global__ void qtilde_kernel(const float* __restrict__ Q, const float* __restrict__ Wk,
                              float* __restrict__ qt) {
    __shared__ float Wks[256 * 33];
    __shared__ float Qs[32 * 32];
    int h  = blockIdx.y;
    int b0 = blockIdx.x * 32;
    int tid = threadIdx.x;
    for (int i = tid; i < 8192; i += 256) {
        int d = i >> 5, j = i & 31;
        Wks[d * 33 + j] = Wk[d * 256 + h * 32 + j];
    }
    #pragma unroll
    for (int p = 0; p < 4; p++) {
        int i = tid + p * 256;
        int r = i >> 5, j = i & 31;
        Qs[i] = Q[(size_t)(b0 + r) * 256 + h * 32 + j];
    }
    __syncthreads();
    int d = tid;
    float w[32];
    #pragma unroll
    for (int j = 0; j < 32; j++) w[j] = Wks[d * 33 + j];
    const float4* Qs4 = reinterpret_cast<const float4*>(Qs);
    #pragma unroll
    for (int half = 0; half < 2; half++) {
        float acc[16];
        #pragma unroll
        for (int r = 0; r < 16; r++) acc[r] = 0.0f;
        #pragma unroll
        for (int r = 0; r < 16; r++) {
            int rr = half * 16 + r;
            #pragma unroll
            for (int j4 = 0; j4 < 8; j4++) {
                float4 q = Qs4[rr * 8 + j4];
                acc[r] += q.x * w[j4 * 4 + 0] + q.y * w[j4 * 4 + 1]
                        + q.z * w[j4 * 4 + 2] + q.w * w[j4 * 4 + 3];
            }
        }
        #pragma unroll
        for (int r = 0; r < 16; r++)
            qt[(size_t)(b0 + half * 16 + r) * 2048 + h * 256 + d] = acc[r];
    }
}

// ---------------- attention core (R4/R6 version), one block per anchor b ----------------
__global__ __launch_bounds__(256)
void attn_kernel(const float* __restrict__ xnei, const float* __restrict__ qt,
                 float* __restrict__ ctx) {
    __shared__ float xs[32 * 260];
    __shared__ float qts[8 * 260];
    __shared__ float sred[8 * 256];
    __shared__ float attns[8 * 32];
    int b    = blockIdx.x;
    int tid  = threadIdx.x;
    int lane = tid & 31;
    int w    = tid >> 5;

    const float4* xb4 = reinterpret_cast<const float4*>(xnei + (size_t)b * 8192);
    #pragma unroll
    for (int j = 0; j < 8; j++) {
        int i  = tid + j * 256;
        int k  = i >> 6;
        int c4 = i & 63;
        *reinterpret_cast<float4*>(xs + k * 260 + c4 * 4) = xb4[i];
    }
    const float4* qrow = reinterpret_cast<const float4*>(qt + (size_t)b * 2048);
    #pragma unroll
    for (int j = 0; j < 2; j++) {
        int i  = tid + j * 256;
        int h  = i >> 6;
        int d4 = i & 63;
        *reinterpret_cast<float4*>(qts + h * 260 + d4 * 4) = qrow[i];
    }
    __syncthreads();

    {
        int k = lane;
        float acc[8];
        #pragma unroll
        for (int h = 0; h < 8; h++) acc[h] = 0.0f;
        const float* xr = xs + k * 260 + w * 32;
        #pragma unroll
        for (int d4 = 0; d4 < 8; d4++) {
            float4 xv = *reinterpret_cast<const float4*>(xr + d4 * 4);
            #pragma unroll
            for (int h = 0; h < 8; h++) {
                float4 qv = *reinterpret_cast<const float4*>(qts + h * 260 + w * 32 + d4 * 4);
                acc[h] = fmaf(qv.x, xv.x, fmaf(qv.y, xv.y,
                          fmaf(qv.z, xv.z, fmaf(qv.w, xv.w, acc[h]))));
            }
        }
        #pragma unroll
        for (int h = 0; h < 8; h++)
            sred[w * 256 + h * 32 + k] = acc[h];
    }
    __syncthreads();

    {
        int h = w, k = lane;
        float sc = 0.0f;
        #pragma unroll
        for (int ww = 0; ww < 8; ww++)
            sc += sred[ww * 256 + h * 32 + k];
        sc *= 0.17677669529663687f;
        float m = sc;
        #pragma unroll
        for (int o = 16; o; o >>= 1) m = fmaxf(m, __shfl_xor_sync(0xFFFFFFFFu, m, o));
        float e = expf(sc - m);
        float s = e;
        #pragma unroll
        for (int o = 16; o; o >>= 1) s += __shfl_xor_sync(0xFFFFFFFFu, s, o);
        attns[h * 32 + k] = e / s;
    }
    __syncthreads();

    {
        int hg  = w >> 2;
        int dqt = w & 3;
        int dbase = dqt * 64 + lane * 2;
        float acc[4][2];
        #pragma unroll
        for (int h = 0; h < 4; h++) { acc[h][0] = 0.f; acc[h][1] = 0.f; }
        #pragma unroll
        for (int k0 = 0; k0 < 32; k0 += 4) {
            float4 a0 = *reinterpret_cast<const float4*>(&attns[(hg * 4 + 0) * 32 + k0]);
            float4 a1 = *reinterpret_cast<const float4*>(&attns[(hg * 4 + 1) * 32 + k0]);
            float4 a2 = *reinterpret_cast<const float4*>(&attns[(hg * 4 + 2) * 32 + k0]);
            float4 a3 = *reinterpret_cast<const float4*>(&attns[(hg * 4 + 3) * 32 + k0]);
            float av0[4] = {a0.x, a0.y, a0.z, a0.w};
            float av1[4] = {a1.x, a1.y, a1.z, a1.w};
            float av2[4] = {a2.x, a2.y, a2.z, a2.w};
            float av3[4] = {a3.x, a3.y, a3.z, a3.w};
            #pragma unroll
            for (int kk = 0; kk < 4; kk++) {
                float2 xv = *reinterpret_cast<const float2*>(xs + (k0 + kk) * 260 + dbase);
                acc[0][0] = fmaf(av0[kk], xv.x, acc[0][0]);
                acc[0][1] = fmaf(av0[kk], xv.y, acc[0][1]);
                acc[1][0] = fmaf(av1[kk], xv.x, acc[1][0]);
                acc[1][1] = fmaf(av1[kk], xv.y, acc[1][1]);
                acc[2][0] = fmaf(av2[kk], xv.x, acc[2][0]);
                acc[2][1] = fmaf(av2[kk], xv.y, acc[2][1]);
                acc[3][0] = fmaf(av3[kk], xv.x, acc[3][0]);
                acc[3][1] = fmaf(av3[kk], xv.y, acc[3][1]);
            }
        }
        float* cb = ctx + (size_t)b * 2048;
        #pragma unroll
        for (int h = 0; h < 4; h++) {
            *reinterpret_cast<float2*>(cb + (hg * 4 + h) * 256 + dbase) =
                make_float2(acc[h][0], acc[h][1]);
        }
    }
}

// ---------------- out[b, h*32+j] = sum_d ctx[b,h,d] * W_v[d, h*32+j] (half out) ----------------
#define VPROJ_SMEM (16384 * 4)
__global__ void vproj_kernel(const float* __restrict__ ctx, const float* __restrict__ Wv,
                             __half* __restrict__ out) {
    extern __shared__ float vsm[];
    float* Wvs = vsm;          // [256][32]
    float* cs  = vsm + 8192;   // [32][256]
    int h  = blockIdx.y;
    int b0 = blockIdx.x * 32;
    int tid = threadIdx.x;
    for (int i = tid * 4; i < 8192; i += 1024) {
        int d = i >> 5, j = i & 31;
        *reinterpret_cast<float4*>(&Wvs[i]) =
            *reinterpret_cast<const float4*>(&Wv[d * 256 + h * 32 + j]);
    }
    for (int i = tid * 4; i < 8192; i += 1024) {
        int r = i >> 8, d2 = i & 255;
        *reinterpret_cast<float4*>(&cs[i]) =
            *reinterpret_cast<const float4*>(&ctx[(size_t)(b0 + r) * 2048 + h * 256 + d2]);
    }
    __syncthreads();
    int j  = tid & 31;
    int rg = tid >> 5;
    float acc0 = 0.0f, acc1 = 0.0f, acc2 = 0.0f, acc3 = 0.0f;
    #pragma unroll 4
    for (int d4 = 0; d4 < 64; d4++) {
        float w0 = Wvs[(d4 * 4 + 0) * 32 + j];
        float w1 = Wvs[(d4 * 4 + 1) * 32 + j];
        float w2 = Wvs[(d4 * 4 + 2) * 32 + j];
        float w3 = Wvs[(d4 * 4 + 3) * 32 + j];
        float4 c0 = *reinterpret_cast<const float4*>(&cs[(rg +  0) * 256 + d4 * 4]);
        float4 c1 = *reinterpret_cast<const float4*>(&cs[(rg +  8) * 256 + d4 * 4]);
        float4 c2 = *reinterpret_cast<const float4*>(&cs[(rg + 16) * 256 + d4 * 4]);
        float4 c3 = *reinterpret_cast<const float4*>(&cs[(rg + 24) * 256 + d4 * 4]);
        acc0 += c0.x * w0 + c0.y * w1 + c0.z * w2 + c0.w * w3;
        acc1 += c1.x * w0 + c1.y * w1 + c1.z * w2 + c1.w * w3;
        acc2 += c2.x * w0 + c2.y * w1 + c2.z * w2 + c2.w * w3;
        acc3 += c3.x * w0 + c3.y * w1 + c3.z * w2 + c3.w * w3;
    }
    out[(size_t)(b0 + rg +  0) * 256 + h * 32 + j] = __float2half_rn(acc0);
    out[(size_t)(b0 + rg +  8) * 256 + h * 32 + j] = __float2half_rn(acc1);
    out[(size_t)(b0 + rg + 16) * 256 + h * 32 + j] = __float2half_rn(acc2);
    out[(size_t)(b0 + rg + 24) * 256 + h * 32 + j] = __float2half_rn(acc3);
}

// ---------------- launcher ----------------
extern "C" void kernel_launch(void* const* d_in, const int* in_sizes, int n_in,
                              void* d_out, int out_size) {
    const float* x_anc = (const float*)d_in[0];
    const float* x_nei = (const float*)d_in[1];
    const float* W_q   = (const float*)d_in[2];
    const float* W_k   = (const float*)d_in[3];
    const float* W_v   = (const float*)d_in[4];
    const float* W_o   = (const float*)d_in[5];
    const float* ln1_g = (const float*)d_in[6];
    const float* ln1_b = (const float*)d_in[7];
    const float* ln2_g = (const float*)d_in[8];
    const float* ln2_b = (const float*)d_in[9];
    const float* ff1_w = (const float*)d_in[10];
    const float* ff1_b = (const float*)d_in[11];
    const float* ff2_w = (const float*)d_in[12];
    const float* ff2_b = (const float*)d_in[13];
    float* out = (float*)d_out;

    __half *p_lnx, *p_att, *p_h, *p_ff, *p_wtq, *p_wto, *p_wt1, *p_wt2;
    float *p_q, *p_qt, *p_ctx, *p_x;
    cudaGetSymbolAddress((void**)&p_lnx, g_lnx);
    cudaGetSymbolAddress((void**)&p_q,   g_q);
    cudaGetSymbolAddress((void**)&p_qt,  g_qt);
    cudaGetSymbolAddress((void**)&p_ctx, g_ctx);
    cudaGetSymbolAddress((void**)&p_att, g_att);
    cudaGetSymbolAddress((void**)&p_x,   g_x);
    cudaGetSymbolAddress((void**)&p_h,   g_h);
    cudaGetSymbolAddress((void**)&p_ff,  g_ff);
    cudaGetSymbolAddress((void**)&p_wtq, g_wtq);
    cudaGetSymbolAddress((void**)&p_wto, g_wto);
    cudaGetSymbolAddress((void**)&p_wt1, g_wt1);
    cudaGetSymbolAddress((void**)&p_wt2, g_wt2);

    cudaFuncSetAttribute(vproj_kernel, cudaFuncAttributeMaxDynamicSharedMemorySize, VPROJ_SMEM);

    dim3 lnBlock(32, 8);
    dim3 tBlock(32, 8);

    // 0. weight transposes -> half [n][k]
    transpose_kernel<<<dim3(8, 8),  tBlock>>>(W_q,   p_wtq, 256, 256);
    transpose_kernel<<<dim3(8, 8),  tBlock>>>(W_o,   p_wto, 256, 256);
    transpose_kernel<<<dim3(32, 8), tBlock>>>(ff1_w, p_wt1, 256, 1024);
    transpose_kernel<<<dim3(8, 32), tBlock>>>(ff2_w, p_wt2, 1024, 256);

    // 1. LN1 -> half
    ln_kernel<<<BN / 8, lnBlock>>>(x_anc, ln1_g, ln1_b, p_lnx);
    // 2. Q = LN1 @ W_q  (fp16 mma.sync, fp32 out)
    hgemm<0><<<dim3(2, BN / 128), 256>>>(p_lnx, p_wtq, p_q, BN, DIM, DIM, nullptr, nullptr);
    // 3. q~ per head (32 anchors/block)
    qtilde_kernel<<<dim3(BN / 32, NH), 256>>>(p_q, W_k, p_qt);
    // 4. attention core -> ctx
    attn_kernel<<<BN, 256>>>(x_nei, p_qt, p_ctx);
    // 5. att = ctx @ W_v (per head, half out)
    vproj_kernel<<<dim3(BN / 32, NH), 256, VPROJ_SMEM>>>(p_ctx, W_v, p_att);
    // 6. x = x_anc + att @ W_o
    hgemm<3><<<dim3(2, BN / 128), 256>>>(p_att, p_wto, p_x, BN, DIM, DIM, nullptr, x_anc);
    // 7. LN2 -> half
    ln_kernel<<<BN / 8, lnBlock>>>(p_x, ln2_g, ln2_b, p_h);
    // 8. ff = gelu(h @ ff1 + b1) (half out)
    hgemm<1><<<dim3(8, BN / 128), 256>>>(p_h, p_wt1, p_ff, BN, NFF, DIM, ff1_b, nullptr);
    // 9. out = x + ff @ ff2 + b2
    hgemm<2><<<dim3(2, BN / 128), 256>>>(p_ff, p_wt2, out, BN, DIM, NFF, ff2_b, p_x);
}

// round 9
// speedup vs baseline: 1.3374x; 1.0774x over previous
#include <cuda_runtime.h>
#include <cuda_fp16.h>
#include <math.h>
#include <stdint.h>

// Problem constants
#define BN  32768
#define DIM 256
#define NK  32
#define NH  8
#define NFF 1024
#define NDK 32

// ---------------- scratch (device globals: allocation-guard-safe) ----------------
__device__ __align__(128) __half g_lnx[BN * DIM];       // LN1(x_anc), half
__device__ __align__(128) float  g_q[BN * DIM];         // Q (fp32, feeds qtilde)
__device__ __align__(128) __half g_qt[BN * NH * DIM];   // q~ [B, H, 256], half
__device__ __align__(128) __half g_ctx[BN * NH * DIM];  // ctx [B, H, 256], half
__device__ __align__(128) __half g_att[BN * DIM];       // attention out (pre-W_o), half
__device__ __align__(128) float  g_x[BN * DIM];         // x = x_anc + att @ W_o
__device__ __align__(128) __half g_h[BN * DIM];         // LN2(x), half
__device__ __align__(128) __half g_ff[BN * NFF];        // gelu(h@ff1+b1), half
// transposed half weights: [n][k] rows
__device__ __align__(128) __half g_wtq[DIM * DIM];
__device__ __align__(128) __half g_wto[DIM * DIM];
__device__ __align__(128) __half g_wt1[DIM * NFF];
__device__ __align__(128) __half g_wt2[NFF * DIM];

// ---------------- LayerNorm: one warp per row, half output ----------------
__global__ void ln_kernel(const float* __restrict__ x, const float* __restrict__ g,
                          const float* __restrict__ b, __half* __restrict__ out) {
    int row  = blockIdx.x * 8 + threadIdx.y;
    int lane = threadIdx.x;
    const float4* xr = reinterpret_cast<const float4*>(x + (size_t)row * DIM);
    float4 v0 = xr[lane];
    float4 v1 = xr[lane + 32];
    float s  = v0.x + v0.y + v0.z + v0.w + v1.x + v1.y + v1.z + v1.w;
    float ss = v0.x*v0.x + v0.y*v0.y + v0.z*v0.z + v0.w*v0.w
             + v1.x*v1.x + v1.y*v1.y + v1.z*v1.z + v1.w*v1.w;
    #pragma unroll
    for (int o = 16; o; o >>= 1) {
        s  += __shfl_xor_sync(0xFFFFFFFFu, s,  o);
        ss += __shfl_xor_sync(0xFFFFFFFFu, ss, o);
    }
    float mu  = s * (1.0f / 256.0f);
    float var = ss * (1.0f / 256.0f) - mu * mu;
    float rs  = rsqrtf(var + 1e-5f);
    const float4* g4 = reinterpret_cast<const float4*>(g);
    const float4* b4 = reinterpret_cast<const float4*>(b);
    __half* orow = out + (size_t)row * DIM;
    #pragma unroll
    for (int p = 0; p < 2; p++) {
        int idx = lane + p * 32;
        float4 v = (p == 0) ? v0 : v1;
        float4 gg = g4[idx], bb = b4[idx];
        float o0 = (v.x - mu) * rs * gg.x + bb.x;
        float o1 = (v.y - mu) * rs * gg.y + bb.y;
        float o2 = (v.z - mu) * rs * gg.z + bb.z;
        float o3 = (v.w - mu) * rs * gg.w + bb.w;
        __half2 ha = __floats2half2_rn(o0, o1);
        __half2 hb = __floats2half2_rn(o2, o3);
        uint2 u;
        u.x = *reinterpret_cast<uint32_t*>(&ha);
        u.y = *reinterpret_cast<uint32_t*>(&hb);
        *reinterpret_cast<uint2*>(orow + idx * 4) = u;
    }
}

__device__ __forceinline__ float gelu_exact(float v) {
    return 0.5f * v * (1.0f + erff(v * 0.70710678118654752f));
}

// ---------------- weight transpose+convert: out[C][R] = (half)in[R][C] ----------------
__global__ void transpose_kernel(const float* __restrict__ in, __half* __restrict__ out,
                                 int R, int C) {
    __shared__ float t[32][33];
    int c0 = blockIdx.x * 32, r0 = blockIdx.y * 32;
    int tx = threadIdx.x, ty = threadIdx.y;   // (32, 8)
    #pragma unroll
    for (int j = 0; j < 4; j++)
        t[ty + j * 8][tx] = in[(size_t)(r0 + ty + j * 8) * C + c0 + tx];
    __syncthreads();
    #pragma unroll
    for (int j = 0; j < 4; j++)
        out[(size_t)(c0 + ty + j * 8) * R + r0 + tx] = __float2half_rn(t[tx][ty + j * 8]);
}

// ================= fp16 tensor-core GEMM: 128x128 tile, m16n8k16 + ldmatrix =================
__device__ __forceinline__ uint32_t smem_u32(const void* p) {
    uint32_t a;
    asm("{ .reg .u64 t; cvta.to.shared.u64 t, %1; cvt.u32.u64 %0, t; }" : "=r"(a) : "l"(p));
    return a;
}
__device__ __forceinline__ void ldsm_x4(uint32_t r[4], uint32_t addr) {
    asm volatile("ldmatrix.sync.aligned.m8n8.x4.shared.b16 {%0,%1,%2,%3}, [%4];"
                 : "=r"(r[0]), "=r"(r[1]), "=r"(r[2]), "=r"(r[3]) : "r"(addr));
}
__device__ __forceinline__ void mma_f16(float c[4], const uint32_t a[4],
                                        uint32_t b0, uint32_t b1) {
    asm volatile(
        "mma.sync.aligned.m16n8k16.row.col.f32.f16.f16.f32 "
        "{%0,%1,%2,%3}, {%4,%5,%6,%7}, {%8,%9}, {%0,%1,%2,%3};\n"
        : "+f"(c[0]), "+f"(c[1]), "+f"(c[2]), "+f"(c[3])
        : "r"(a[0]), "r"(a[1]), "r"(a[2]), "r"(a[3]), "r"(b0), "r"(b1));
}

#define HS 40                     // halves per smem row
#define HBUF (128 * HS * 2)       // bytes per buffer

// MODE 0: C=A@B (f32)   1: gelu(A@B+bias) (HALF out)   2: A@B+bias+resid (f32)   3: A@B+resid (f32)
template <int MODE>
__global__ __launch_bounds__(256, 2)
void hgemm(const __half* __restrict__ A, const __half* __restrict__ BT,
           void* __restrict__ Cout, int M, int N, int Kd,
           const float* __restrict__ bias, const float* __restrict__ resid) {
    __shared__ __half As[2][128][HS];
    __shared__ __half Bs[2][128][HS];

    const int tid  = threadIdx.x;
    const int lane = tid & 31;
    const int wid  = tid >> 5;
    const int m0 = blockIdx.y * 128;
    const int n0 = blockIdx.x * 128;
    const int warp_m = (wid & 1) * 64;
    const int warp_n = (wid >> 1) * 32;

    const int ldRow = tid >> 1;
    const int ldCol = (tid & 1) * 16;
    const __half* Ag = A  + (size_t)(m0 + ldRow) * Kd + ldCol;
    const __half* Bg = BT + (size_t)(n0 + ldRow) * Kd + ldCol;

    float c[4][4][4];
    #pragma unroll
    for (int mt = 0; mt < 4; mt++)
        #pragma unroll
        for (int nt = 0; nt < 4; nt++)
            #pragma unroll
            for (int i = 0; i < 4; i++) c[mt][nt][i] = 0.0f;

    const uint32_t as_base = smem_u32(&As[0][0][0]);
    const uint32_t bs_base = smem_u32(&Bs[0][0][0]);
    const int a_row = warp_m + (lane & 7) + ((lane >> 3) & 1) * 8;
    const int a_k   = (lane >> 4) * 8;
    const int b_row = warp_n + (lane & 7) + ((lane >> 4) & 1) * 8;
    const int b_k   = ((lane >> 3) & 1) * 8;
    const uint32_t aAddr0 = as_base + (uint32_t)(a_row * HS + a_k) * 2;
    const uint32_t bAddr0 = bs_base + (uint32_t)(b_row * HS + b_k) * 2;

    uint4 av0 = *reinterpret_cast<const uint4*>(Ag);
    uint4 av1 = *reinterpret_cast<const uint4*>(Ag + 8);
    uint4 bv0 = *reinterpret_cast<const uint4*>(Bg);
    uint4 bv1 = *reinterpret_cast<const uint4*>(Bg + 8);
    *reinterpret_cast<uint4*>(&As[0][ldRow][ldCol])     = av0;
    *reinterpret_cast<uint4*>(&As[0][ldRow][ldCol + 8]) = av1;
    *reinterpret_cast<uint4*>(&Bs[0][ldRow][ldCol])     = bv0;
    *reinterpret_cast<uint4*>(&Bs[0][ldRow][ldCol + 8]) = bv1;
    __syncthreads();

    const int KT = Kd >> 5;
    int buf = 0;
    for (int kt = 0; kt < KT; kt++) {
        if (kt + 1 < KT) {
            const __half* Ap = Ag + (kt + 1) * 32;
            const __half* Bp = Bg + (kt + 1) * 32;
            av0 = *reinterpret_cast<const uint4*>(Ap);
            av1 = *reinterpret_cast<const uint4*>(Ap + 8);
            bv0 = *reinterpret_cast<const uint4*>(Bp);
            bv1 = *reinterpret_cast<const uint4*>(Bp + 8);
        }
        const uint32_t bo = (uint32_t)buf * HBUF;
        #pragma unroll
        for (int ks = 0; ks < 2; ks++) {
            uint32_t af[4][4];
            uint32_t bf[2][4];
            #pragma unroll
            for (int mt = 0; mt < 4; mt++)
                ldsm_x4(af[mt], aAddr0 + bo + (uint32_t)(mt * 16 * HS + ks * 16) * 2);
            #pragma unroll
            for (int ntp = 0; ntp < 2; ntp++)
                ldsm_x4(bf[ntp], bAddr0 + bo + (uint32_t)(ntp * 16 * HS + ks * 16) * 2);
            #pragma unroll
            for (int mt = 0; mt < 4; mt++) {
                #pragma unroll
                for (int nt = 0; nt < 4; nt++) {
                    uint32_t b0 = (nt & 1) ? bf[nt >> 1][2] : bf[nt >> 1][0];
                    uint32_t b1 = (nt & 1) ? bf[nt >> 1][3] : bf[nt >> 1][1];
                    mma_f16(c[mt][nt], af[mt], b0, b1);
                }
            }
        }
        if (kt + 1 < KT) {
            buf ^= 1;
            *reinterpret_cast<uint4*>(&As[buf][ldRow][ldCol])     = av0;
            *reinterpret_cast<uint4*>(&As[buf][ldRow][ldCol + 8]) = av1;
            *reinterpret_cast<uint4*>(&Bs[buf][ldRow][ldCol])     = bv0;
            *reinterpret_cast<uint4*>(&Bs[buf][ldRow][ldCol + 8]) = bv1;
        }
        __syncthreads();
    }

    const int fr = lane >> 2;
    const int fc = lane & 3;
    #pragma unroll
    for (int mt = 0; mt < 4; mt++) {
        #pragma unroll
        for (int nt = 0; nt < 4; nt++) {
            int row0 = m0 + warp_m + mt * 16 + fr;
            int col  = n0 + warp_n + nt * 8 + fc * 2;
            float v0 = c[mt][nt][0], v1 = c[mt][nt][1];
            float v2 = c[mt][nt][2], v3 = c[mt][nt][3];
            if (MODE == 1 || MODE == 2) {
                float2 bv = *reinterpret_cast<const float2*>(bias + col);
                v0 += bv.x; v1 += bv.y; v2 += bv.x; v3 += bv.y;
            }
            if (MODE == 1) {
                v0 = gelu_exact(v0); v1 = gelu_exact(v1);
                v2 = gelu_exact(v2); v3 = gelu_exact(v3);
            }
            if (MODE == 2 || MODE == 3) {
                float2 r0 = *reinterpret_cast<const float2*>(resid + (size_t)row0 * N + col);
                float2 r1 = *reinterpret_cast<const float2*>(resid + (size_t)(row0 + 8) * N + col);
                v0 += r0.x; v1 += r0.y; v2 += r1.x; v3 += r1.y;
            }
            if (MODE == 1) {
                __half* Ch = reinterpret_cast<__half*>(Cout);
                __half2 h0 = __floats2half2_rn(v0, v1);
                __half2 h1 = __floats2half2_rn(v2, v3);
                *reinterpret_cast<__half2*>(Ch + (size_t)row0 * N + col)       = h0;
                *reinterpret_cast<__half2*>(Ch + (size_t)(row0 + 8) * N + col) = h1;
            } else {
                float* Cf = reinterpret_cast<float*>(Cout);
                *reinterpret_cast<float2*>(Cf + (size_t)row0 * N + col)       = make_float2(v0, v1);
                *reinterpret_cast<float2*>(Cf + (size_t)(row0 + 8) * N + col) = make_float2(v2, v3);
            }
        }
    }
}

// ---------------- q~[b,h,d] = sum_j Q[b, h*32+j] * W_k[d, h*32+j]  (half out) ----------------
__global__ void qtilde_kernel(const float* __restrict__ Q, const float* __restrict__ Wk,
                              __half* __restrict__ qt) {
    __shared__ float Wks[256 * 33];
    __shared__ float Qs[32 * 32];
    int h  = blockIdx.y;
    int b0 = blockIdx.x * 32;
    int tid = threadIdx.x;
    for (int i = tid; i < 8192; i += 256) {
        int d = i >> 5, j = i & 31;
        Wks[d * 33 + j] = Wk[d * 256 + h * 32 + j];
    }
    #pragma unroll
    for (int p = 0; p < 4; p++) {
        int i = tid + p * 256;
        int r = i >> 5, j = i & 31;
        Qs[i] = Q[(size_t)(b0 + r) * 256 + h * 32 + j];
    }
    __syncthreads();
    int d = tid;
    float w[32];
    #pragma unroll
    for (int j = 0; j < 32; j++) w[j] = Wks[d * 33 + j];
    const float4* Qs4 = reinterpret_cast<const float4*>(Qs);
    #pragma unroll
    for (int half = 0; half < 2; half++) {
        float acc[16];
        #pragma unroll
        for (int r = 0; r < 16; r++) acc[r] = 0.0f;
        #pragma unroll
        for (int r = 0; r < 16; r++) {
            int rr = half * 16 + r;
            #pragma unroll
            for (int j4 = 0; j4 < 8; j4++) {
                float4 q = Qs4[rr * 8 + j4];
                acc[r] += q.x * w[j4 * 4 + 0] + q.y * w[j4 * 4 + 1]
                        + q.z * w[j4 * 4 + 2] + q.w * w[j4 * 4 + 3];
            }
        }
        #pragma unroll
        for (int r = 0; r < 16; r++)
            qt[(size_t)(b0 + half * 16 + r) * 2048 + h * 256 + d] = __float2half_rn(acc[r]);
    }
}

// ---------------- attention core v5: half-staged x and q ----------------
// xs stride 260 halves (520B = 8 mod 128 -> conflict-free 8B loads);
// qts stride 264 halves (528B, 16B-aligned for uint4 staging; q loads are broadcasts).
#define XS_H 260
#define QS_H 264
__global__ __launch_bounds__(256)
void attn_kernel(const float* __restrict__ xnei, const __half* __restrict__ qt,
                 __half* __restrict__ ctx) {
    __shared__ __half xs[32 * XS_H];
    __shared__ __half qts[8 * QS_H];
    __shared__ float sred[8 * 256];
    __shared__ float attns[8 * 32];
    int b    = blockIdx.x;
    int tid  = threadIdx.x;
    int lane = tid & 31;
    int w    = tid >> 5;

    // stage x_nei[b] fp32 -> half
    const float4* xb4 = reinterpret_cast<const float4*>(xnei + (size_t)b * 8192);
    #pragma unroll
    for (int j = 0; j < 8; j++) {
        int i  = tid + j * 256;
        int k  = i >> 6;
        int c4 = i & 63;
        float4 v = xb4[i];
        __half2 h0 = __floats2half2_rn(v.x, v.y);
        __half2 h1 = __floats2half2_rn(v.z, v.w);
        uint2 u;
        u.x = *reinterpret_cast<uint32_t*>(&h0);
        u.y = *reinterpret_cast<uint32_t*>(&h1);
        *reinterpret_cast<uint2*>(xs + k * XS_H + c4 * 4) = u;
    }
    // stage q~[b] (half in DRAM)
    {
        const uint4* qp = reinterpret_cast<const uint4*>(qt + (size_t)b * 2048);
        int h  = tid >> 5;
        int c8 = tid & 31;
        *reinterpret_cast<uint4*>(qts + h * QS_H + c8 * 8) = qp[tid];
    }
    __syncthreads();

    // ---- phase 1: warp w covers d in [w*32, w*32+32), lane = k, 8 head partials ----
    {
        int k = lane;
        float acc[8];
        #pragma unroll
        for (int h = 0; h < 8; h++) acc[h] = 0.0f;
        const __half* xr = xs + k * XS_H + w * 32;
        #pragma unroll
        for (int d4 = 0; d4 < 8; d4++) {
            uint2 xu = *reinterpret_cast<const uint2*>(xr + d4 * 4);
            float2 xf0 = __half22float2(*reinterpret_cast<__half2*>(&xu.x));
            float2 xf1 = __half22float2(*reinterpret_cast<__half2*>(&xu.y));
            #pragma unroll
            for (int h = 0; h < 8; h++) {
                uint2 qu = *reinterpret_cast<const uint2*>(qts + h * QS_H + w * 32 + d4 * 4);
                float2 qf0 = __half22float2(*reinterpret_cast<__half2*>(&qu.x));
                float2 qf1 = __half22float2(*reinterpret_cast<__half2*>(&qu.y));
                acc[h] = fmaf(qf0.x, xf0.x, fmaf(qf0.y, xf0.y,
                          fmaf(qf1.x, xf1.x, fmaf(qf1.y, xf1.y, acc[h]))));
            }
        }
        #pragma unroll
        for (int h = 0; h < 8; h++)
            sred[w * 256 + h * 32 + k] = acc[h];
    }
    __syncthreads();

    // ---- softmax: warp w handles head h=w, lane = k ----
    {
        int h = w, k = lane;
        float sc = 0.0f;
        #pragma unroll
        for (int ww = 0; ww < 8; ww++)
            sc += sred[ww * 256 + h * 32 + k];
        sc *= 0.17677669529663687f;
        float m = sc;
        #pragma unroll
        for (int o = 16; o; o >>= 1) m = fmaxf(m, __shfl_xor_sync(0xFFFFFFFFu, m, o));
        float e = expf(sc - m);
        float s = e;
        #pragma unroll
        for (int o = 16; o; o >>= 1) s += __shfl_xor_sync(0xFFFFFFFFu, s, o);
        attns[h * 32 + k] = e / s;
    }
    __syncthreads();

    // ---- phase 2: ctx; warp = (4-head group, d-quarter), lane = d-pair ----
    {
        int hg  = w >> 2;
        int dqt = w & 3;
        int dbase = dqt * 64 + lane * 2;
        float acc[4][2];
        #pragma unroll
        for (int h = 0; h < 4; h++) { acc[h][0] = 0.f; acc[h][1] = 0.f; }
        #pragma unroll
        for (int k0 = 0; k0 < 32; k0 += 4) {
            float4 a0 = *reinterpret_cast<const float4*>(&attns[(hg * 4 + 0) * 32 + k0]);
            float4 a1 = *reinterpret_cast<const float4*>(&attns[(hg * 4 + 1) * 32 + k0]);
            float4 a2 = *reinterpret_cast<const float4*>(&attns[(hg * 4 + 2) * 32 + k0]);
            float4 a3 = *reinterpret_cast<const float4*>(&attns[(hg * 4 + 3) * 32 + k0]);
            float av0[4] = {a0.x, a0.y, a0.z, a0.w};
            float av1[4] = {a1.x, a1.y, a1.z, a1.w};
            float av2[4] = {a2.x, a2.y, a2.z, a2.w};
            float av3[4] = {a3.x, a3.y, a3.z, a3.w};
            #pragma unroll
            for (int kk = 0; kk < 4; kk++) {
                uint32_t xu = *reinterpret_cast<const uint32_t*>(xs + (k0 + kk) * XS_H + dbase);
                float2 xv = __half22float2(*reinterpret_cast<__half2*>(&xu));
                acc[0][0] = fmaf(av0[kk], xv.x, acc[0][0]);
                acc[0][1] = fmaf(av0[kk], xv.y, acc[0][1]);
                acc[1][0] = fmaf(av1[kk], xv.x, acc[1][0]);
                acc[1][1] = fmaf(av1[kk], xv.y, acc[1][1]);
                acc[2][0] = fmaf(av2[kk], xv.x, acc[2][0]);
                acc[2][1] = fmaf(av2[kk], xv.y, acc[2][1]);
                acc[3][0] = fmaf(av3[kk], xv.x, acc[3][0]);
                acc[3][1] = fmaf(av3[kk], xv.y, acc[3][1]);
            }
        }
        __half* cb = ctx + (size_t)b * 2048;
        #pragma unroll
        for (int h = 0; h < 4; h++) {
            __half2 hv = __floats2half2_rn(acc[h][0], acc[h][1]);
            *reinterpret_cast<__half2*>(cb + (hg * 4 + h) * 256 + dbase) = hv;
        }
    }
}

// ---------------- out[b, h*32+j] = sum_d ctx[b,h,d] * W_v[d, h*32+j] (half in/out) ----------------
#define VPROJ_SMEM (16384 * 4)
__global__ void vproj_kernel(const __half* __restrict__ ctx, const float* __restrict__ Wv,
                             __half* __restrict__ out) {
    extern __shared__ float vsm[];
    float* Wvs = vsm;          // [256][32]
    float* cs  = vsm + 8192;   // [32][256]
    int h  = blockIdx.y;
    int b0 = blockIdx.x * 32;
    int tid = threadIdx.x;
    for (int i = tid * 4; i < 8192; i += 1024) {
        int d = i >> 5, j = i & 31;
        *reinterpret_cast<float4*>(&Wvs[i]) =
            *reinterpret_cast<const float4*>(&Wv[d * 256 + h * 32 + j]);
    }
    for (int i = tid * 8; i < 8192; i += 2048) {
        int r = i >> 8, d2 = i & 255;
        uint4 u = *reinterpret_cast<const uint4*>(&ctx[(size_t)(b0 + r) * 2048 + h * 256 + d2]);
        float2 f0 = __half22float2(*reinterpret_cast<__half2*>(&u.x));
        float2 f1 = __half22float2(*reinterpret_cast<__half2*>(&u.y));
        float2 f2 = __half22float2(*reinterpret_cast<__half2*>(&u.z));
        float2 f3 = __half22float2(*reinterpret_cast<__half2*>(&u.w));
        *reinterpret_cast<float4*>(&cs[i])     = make_float4(f0.x, f0.y, f1.x, f1.y);
        *reinterpret_cast<float4*>(&cs[i + 4]) = make_float4(f2.x, f2.y, f3.x, f3.y);
    }
    __syncthreads();
    int j  = tid & 31;
    int rg = tid >> 5;
    float acc0 = 0.0f, acc1 = 0.0f, acc2 = 0.0f, acc3 = 0.0f;
    #pragma unroll 4
    for (int d4 = 0; d4 < 64; d4++) {
        float w0 = Wvs[(d4 * 4 + 0) * 32 + j];
        float w1 = Wvs[(d4 * 4 + 1) * 32 + j];
        float w2 = Wvs[(d4 * 4 + 2) * 32 + j];
        float w3 = Wvs[(d4 * 4 + 3) * 32 + j];
        float4 c0 = *reinterpret_cast<const float4*>(&cs[(rg +  0) * 256 + d4 * 4]);
        float4 c1 = *reinterpret_cast<const float4*>(&cs[(rg +  8) * 256 + d4 * 4]);
        float4 c2 = *reinterpret_cast<const float4*>(&cs[(rg + 16) * 256 + d4 * 4]);
        float4 c3 = *reinterpret_cast<const float4*>(&cs[(rg + 24) * 256 + d4 * 4]);
        acc0 += c0.x * w0 + c0.y * w1 + c0.z * w2 + c0.w * w3;
        acc1 += c1.x * w0 + c1.y * w1 + c1.z * w2 + c1.w * w3;
        acc2 += c2.x * w0 + c2.y * w1 + c2.z * w2 + c2.w * w3;
        acc3 += c3.x * w0 + c3.y * w1 + c3.z * w2 + c3.w * w3;
    }
    out[(size_t)(b0 + rg +  0) * 256 + h * 32 + j] = __float2half_rn(acc0);
    out[(size_t)(b0 + rg +  8) * 256 + h * 32 + j] = __float2half_rn(acc1);
    out[(size_t)(b0 + rg + 16) * 256 + h * 32 + j] = __float2half_rn(acc2);
    out[(size_t)(b0 + rg + 24) * 256 + h * 32 + j] = __float2half_rn(acc3);
}

// ---------------- launcher ----------------
extern "C" void kernel_launch(void* const* d_in, const int* in_sizes, int n_in,
                              void* d_out, int out_size) {
    const float* x_anc = (const float*)d_in[0];
    const float* x_nei = (const float*)d_in[1];
    const float* W_q   = (const float*)d_in[2];
    const float* W_k   = (const float*)d_in[3];
    const float* W_v   = (const float*)d_in[4];
    const float* W_o   = (const float*)d_in[5];
    const float* ln1_g = (const float*)d_in[6];
    const float* ln1_b = (const float*)d_in[7];
    const float* ln2_g = (const float*)d_in[8];
    const float* ln2_b = (const float*)d_in[9];
    const float* ff1_w = (const float*)d_in[10];
    const float* ff1_b = (const float*)d_in[11];
    const float* ff2_w = (const float*)d_in[12];
    const float* ff2_b = (const float*)d_in[13];
    float* out = (float*)d_out;

    __half *p_lnx, *p_qt, *p_ctx, *p_att, *p_h, *p_ff, *p_wtq, *p_wto, *p_wt1, *p_wt2;
    float *p_q, *p_x;
    cudaGetSymbolAddress((void**)&p_lnx, g_lnx);
    cudaGetSymbolAddress((void**)&p_q,   g_q);
    cudaGetSymbolAddress((void**)&p_qt,  g_qt);
    cudaGetSymbolAddress((void**)&p_ctx, g_ctx);
    cudaGetSymbolAddress((void**)&p_att, g_att);
    cudaGetSymbolAddress((void**)&p_x,   g_x);
    cudaGetSymbolAddress((void**)&p_h,   g_h);
    cudaGetSymbolAddress((void**)&p_ff,  g_ff);
    cudaGetSymbolAddress((void**)&p_wtq, g_wtq);
    cudaGetSymbolAddress((void**)&p_wto, g_wto);
    cudaGetSymbolAddress((void**)&p_wt1, g_wt1);
    cudaGetSymbolAddress((void**)&p_wt2, g_wt2);

    cudaFuncSetAttribute(vproj_kernel, cudaFuncAttributeMaxDynamicSharedMemorySize, VPROJ_SMEM);

    dim3 lnBlock(32, 8);
    dim3 tBlock(32, 8);

    // 0. weight transposes -> half [n][k]
    transpose_kernel<<<dim3(8, 8),  tBlock>>>(W_q,   p_wtq, 256, 256);
    transpose_kernel<<<dim3(8, 8),  tBlock>>>(W_o,   p_wto, 256, 256);
    transpose_kernel<<<dim3(32, 8), tBlock>>>(ff1_w, p_wt1, 256, 1024);
    transpose_kernel<<<dim3(8, 32), tBlock>>>(ff2_w, p_wt2, 1024, 256);

    // 1. LN1 -> half
    ln_kernel<<<BN / 8, lnBlock>>>(x_anc, ln1_g, ln1_b, p_lnx);
    // 2. Q = LN1 @ W_q  (fp16 mma.sync, fp32 out)
    hgemm<0><<<dim3(2, BN / 128), 256>>>(p_lnx, p_wtq, p_q, BN, DIM, DIM, nullptr, nullptr);
    // 3. q~ per head (32 anchors/block, half out)
    qtilde_kernel<<<dim3(BN / 32, NH), 256>>>(p_q, W_k, p_qt);
    // 4. attention core -> ctx (half)
    attn_kernel<<<BN, 256>>>(x_nei, p_qt, p_ctx);
    // 5. att = ctx @ W_v (per head, half in/out)
    vproj_kernel<<<dim3(BN / 32, NH), 256, VPROJ_SMEM>>>(p_ctx, W_v, p_att);
    // 6. x = x_anc + att @ W_o
    hgemm<3><<<dim3(2, BN / 128), 256>>>(p_att, p_wto, p_x, BN, DIM, DIM, nullptr, x_anc);
    // 7. LN2 -> half
    ln_kernel<<<BN / 8, lnBlock>>>(p_x, ln2_g, ln2_b, p_h);
    // 8. ff = gelu(h @ ff1 + b1) (half out)
    hgemm<1><<<dim3(8, BN / 128), 256>>>(p_h, p_wt1, p_ff, BN, NFF, DIM, ff1_b, nullptr);
    // 9. out = x + ff @ ff2 + b2
    hgemm<2><<<dim3(2, BN / 128), 256>>>(p_ff, p_wt2, out, BN, DIM, NFF, ff2_b, p_x);
}

// round 10
// speedup vs baseline: 1.4287x; 1.0683x over previous
#include <cuda_runtime.h>
#include <cuda_fp16.h>
#include <math.h>
#include <stdint.h>

// Problem constants
#define BN  32768
#define DIM 256
#define NK  32
#define NH  8
#define NFF 1024
#define NDK 32

// ---------------- scratch (device globals: allocation-guard-safe) ----------------
__device__ __align__(128) __half g_lnx[BN * DIM];       // LN1(x_anc), half
__device__ __align__(128) float  g_q[BN * DIM];         // Q (fp32, feeds qtilde)
__device__ __align__(128) __half g_qt[BN * NH * DIM];   // q~ [B, H, 256], half
__device__ __align__(128) __half g_ctx[BN * NH * DIM];  // ctx [B, H, 256], half
__device__ __align__(128) __half g_att[BN * DIM];       // attention out (pre-W_o), half
__device__ __align__(128) float  g_x[BN * DIM];         // x = x_anc + att @ W_o
__device__ __align__(128) __half g_h[BN * DIM];         // LN2(x), half
__device__ __align__(128) __half g_ff[BN * NFF];        // gelu(h@ff1+b1), half
// transposed half weights: [n][k] rows
__device__ __align__(128) __half g_wtq[DIM * DIM];
__device__ __align__(128) __half g_wto[DIM * DIM];
__device__ __align__(128) __half g_wt1[DIM * NFF];
__device__ __align__(128) __half g_wt2[NFF * DIM];

// ---------------- LayerNorm: one warp per row, half output ----------------
__global__ void ln_kernel(const float* __restrict__ x, const float* __restrict__ g,
                          const float* __restrict__ b, __half* __restrict__ out) {
    int row  = blockIdx.x * 8 + threadIdx.y;
    int lane = threadIdx.x;
    const float4* xr = reinterpret_cast<const float4*>(x + (size_t)row * DIM);
    float4 v0 = xr[lane];
    float4 v1 = xr[lane + 32];
    float s  = v0.x + v0.y + v0.z + v0.w + v1.x + v1.y + v1.z + v1.w;
    float ss = v0.x*v0.x + v0.y*v0.y + v0.z*v0.z + v0.w*v0.w
             + v1.x*v1.x + v1.y*v1.y + v1.z*v1.z + v1.w*v1.w;
    #pragma unroll
    for (int o = 16; o; o >>= 1) {
        s  += __shfl_xor_sync(0xFFFFFFFFu, s,  o);
        ss += __shfl_xor_sync(0xFFFFFFFFu, ss, o);
    }
    float mu  = s * (1.0f / 256.0f);
    float var = ss * (1.0f / 256.0f) - mu * mu;
    float rs  = rsqrtf(var + 1e-5f);
    const float4* g4 = reinterpret_cast<const float4*>(g);
    const float4* b4 = reinterpret_cast<const float4*>(b);
    __half* orow = out + (size_t)row * DIM;
    #pragma unroll
    for (int p = 0; p < 2; p++) {
        int idx = lane + p * 32;
        float4 v = (p == 0) ? v0 : v1;
        float4 gg = g4[idx], bb = b4[idx];
        float o0 = (v.x - mu) * rs * gg.x + bb.x;
        float o1 = (v.y - mu) * rs * gg.y + bb.y;
        float o2 = (v.z - mu) * rs * gg.z + bb.z;
        float o3 = (v.w - mu) * rs * gg.w + bb.w;
        __half2 ha = __floats2half2_rn(o0, o1);
        __half2 hb = __floats2half2_rn(o2, o3);
        uint2 u;
        u.x = *reinterpret_cast<uint32_t*>(&ha);
        u.y = *reinterpret_cast<uint32_t*>(&hb);
        *reinterpret_cast<uint2*>(orow + idx * 4) = u;
    }
}

__device__ __forceinline__ float gelu_exact(float v) {
    return 0.5f * v * (1.0f + erff(v * 0.70710678118654752f));
}

// ---------------- weight transpose+convert: out[C][R] = (half)in[R][C] ----------------
__global__ void transpose_kernel(const float* __restrict__ in, __half* __restrict__ out,
                                 int R, int C) {
    __shared__ float t[32][33];
    int c0 = blockIdx.x * 32, r0 = blockIdx.y * 32;
    int tx = threadIdx.x, ty = threadIdx.y;   // (32, 8)
    #pragma unroll
    for (int j = 0; j < 4; j++)
        t[ty + j * 8][tx] = in[(size_t)(r0 + ty + j * 8) * C + c0 + tx];
    __syncthreads();
    #pragma unroll
    for (int j = 0; j < 4; j++)
        out[(size_t)(c0 + ty + j * 8) * R + r0 + tx] = __float2half_rn(t[tx][ty + j * 8]);
}

// ---------------- shared helpers ----------------
__device__ __forceinline__ uint32_t smem_u32(const void* p) {
    uint32_t a;
    asm("{ .reg .u64 t; cvta.to.shared.u64 t, %1; cvt.u32.u64 %0, t; }" : "=r"(a) : "l"(p));
    return a;
}
__device__ __forceinline__ void ldsm_x4(uint32_t r[4], uint32_t addr) {
    asm volatile("ldmatrix.sync.aligned.m8n8.x4.shared.b16 {%0,%1,%2,%3}, [%4];"
                 : "=r"(r[0]), "=r"(r[1]), "=r"(r[2]), "=r"(r[3]) : "r"(addr));
}
__device__ __forceinline__ void ldsm_x4_trans(uint32_t r[4], uint32_t addr) {
    asm volatile("ldmatrix.sync.aligned.m8n8.x4.trans.shared.b16 {%0,%1,%2,%3}, [%4];"
                 : "=r"(r[0]), "=r"(r[1]), "=r"(r[2]), "=r"(r[3]) : "r"(addr));
}
__device__ __forceinline__ void ldsm_x2(uint32_t r[2], uint32_t addr) {
    asm volatile("ldmatrix.sync.aligned.m8n8.x2.shared.b16 {%0,%1}, [%2];"
                 : "=r"(r[0]), "=r"(r[1]) : "r"(addr));
}
__device__ __forceinline__ void mma_f16(float c[4], const uint32_t a[4],
                                        uint32_t b0, uint32_t b1) {
    asm volatile(
        "mma.sync.aligned.m16n8k16.row.col.f32.f16.f16.f32 "
        "{%0,%1,%2,%3}, {%4,%5,%6,%7}, {%8,%9}, {%0,%1,%2,%3};\n"
        : "+f"(c[0]), "+f"(c[1]), "+f"(c[2]), "+f"(c[3])
        : "r"(a[0]), "r"(a[1]), "r"(a[2]), "r"(a[3]), "r"(b0), "r"(b1));
}

// ================= fp16 tensor-core GEMM (R8/R9 version) =================
#define HS 40
#define HBUF (128 * HS * 2)

// MODE 0: C=A@B (f32)   1: gelu(A@B+bias) (HALF out)   2: A@B+bias+resid (f32)   3: A@B+resid (f32)
template <int MODE>
__global__ __launch_bounds__(256, 2)
void hgemm(const __half* __restrict__ A, const __half* __restrict__ BT,
           void* __restrict__ Cout, int M, int N, int Kd,
           const float* __restrict__ bias, const float* __restrict__ resid) {
    __shared__ __half As[2][128][HS];
    __shared__ __half Bs[2][128][HS];

    const int tid  = threadIdx.x;
    const int lane = tid & 31;
    const int wid  = tid >> 5;
    const int m0 = blockIdx.y * 128;
    const int n0 = blockIdx.x * 128;
    const int warp_m = (wid & 1) * 64;
    const int warp_n = (wid >> 1) * 32;

    const int ldRow = tid >> 1;
    const int ldCol = (tid & 1) * 16;
    const __half* Ag = A  + (size_t)(m0 + ldRow) * Kd + ldCol;
    const __half* Bg = BT + (size_t)(n0 + ldRow) * Kd + ldCol;

    float c[4][4][4];
    #pragma unroll
    for (int mt = 0; mt < 4; mt++)
        #pragma unroll
        for (int nt = 0; nt < 4; nt++)
            #pragma unroll
            for (int i = 0; i < 4; i++) c[mt][nt][i] = 0.0f;

    const uint32_t as_base = smem_u32(&As[0][0][0]);
    const uint32_t bs_base = smem_u32(&Bs[0][0][0]);
    const int a_row = warp_m + (lane & 7) + ((lane >> 3) & 1) * 8;
    const int a_k   = (lane >> 4) * 8;
    const int b_row = warp_n + (lane & 7) + ((lane >> 4) & 1) * 8;
    const int b_k   = ((lane >> 3) & 1) * 8;
    const uint32_t aAddr0 = as_base + (uint32_t)(a_row * HS + a_k) * 2;
    const uint32_t bAddr0 = bs_base + (uint32_t)(b_row * HS + b_k) * 2;

    uint4 av0 = *reinterpret_cast<const uint4*>(Ag);
    uint4 av1 = *reinterpret_cast<const uint4*>(Ag + 8);
    uint4 bv0 = *reinterpret_cast<const uint4*>(Bg);
    uint4 bv1 = *reinterpret_cast<const uint4*>(Bg + 8);
    *reinterpret_cast<uint4*>(&As[0][ldRow][ldCol])     = av0;
    *reinterpret_cast<uint4*>(&As[0][ldRow][ldCol + 8]) = av1;
    *reinterpret_cast<uint4*>(&Bs[0][ldRow][ldCol])     = bv0;
    *reinterpret_cast<uint4*>(&Bs[0][ldRow][ldCol + 8]) = bv1;
    __syncthreads();

    const int KT = Kd >> 5;
    int buf = 0;
    for (int kt = 0; kt < KT; kt++) {
        if (kt + 1 < KT) {
            const __half* Ap = Ag + (kt + 1) * 32;
            const __half* Bp = Bg + (kt + 1) * 32;
            av0 = *reinterpret_cast<const uint4*>(Ap);
            av1 = *reinterpret_cast<const uint4*>(Ap + 8);
            bv0 = *reinterpret_cast<const uint4*>(Bp);
            bv1 = *reinterpret_cast<const uint4*>(Bp + 8);
        }
        const uint32_t bo = (uint32_t)buf * HBUF;
        #pragma unroll
        for (int ks = 0; ks < 2; ks++) {
            uint32_t af[4][4];
            uint32_t bf[2][4];
            #pragma unroll
            for (int mt = 0; mt < 4; mt++)
                ldsm_x4(af[mt], aAddr0 + bo + (uint32_t)(mt * 16 * HS + ks * 16) * 2);
            #pragma unroll
            for (int ntp = 0; ntp < 2; ntp++)
                ldsm_x4(bf[ntp], bAddr0 + bo + (uint32_t)(ntp * 16 * HS + ks * 16) * 2);
            #pragma unroll
            for (int mt = 0; mt < 4; mt++) {
                #pragma unroll
                for (int nt = 0; nt < 4; nt++) {
                    uint32_t b0 = (nt & 1) ? bf[nt >> 1][2] : bf[nt >> 1][0];
                    uint32_t b1 = (nt & 1) ? bf[nt >> 1][3] : bf[nt >> 1][1];
                    mma_f16(c[mt][nt], af[mt], b0, b1);
                }
            }
        }
        if (kt + 1 < KT) {
            buf ^= 1;
            *reinterpret_cast<uint4*>(&As[buf][ldRow][ldCol])     = av0;
            *reinterpret_cast<uint4*>(&As[buf][ldRow][ldCol + 8]) = av1;
            *reinterpret_cast<uint4*>(&Bs[buf][ldRow][ldCol])     = bv0;
            *reinterpret_cast<uint4*>(&Bs[buf][ldRow][ldCol + 8]) = bv1;
        }
        __syncthreads();
    }

    const int fr = lane >> 2;
    const int fc = lane & 3;
    #pragma unroll
    for (int mt = 0; mt < 4; mt++) {
        #pragma unroll
        for (int nt = 0; nt < 4; nt++) {
            int row0 = m0 + warp_m + mt * 16 + fr;
            int col  = n0 + warp_n + nt * 8 + fc * 2;
            float v0 = c[mt][nt][0], v1 = c[mt][nt][1];
            float v2 = c[mt][nt][2], v3 = c[mt][nt][3];
            if (MODE == 1 || MODE == 2) {
                float2 bv = *reinterpret_cast<const float2*>(bias + col);
                v0 += bv.x; v1 += bv.y; v2 += bv.x; v3 += bv.y;
            }
            if (MODE == 1) {
                v0 = gelu_exact(v0); v1 = gelu_exact(v1);
                v2 = gelu_exact(v2); v3 = gelu_exact(v3);
            }
            if (MODE == 2 || MODE == 3) {
                float2 r0 = *reinterpret_cast<const float2*>(resid + (size_t)row0 * N + col);
                float2 r1 = *reinterpret_cast<const float2*>(resid + (size_t)(row0 + 8) * N + col);
                v0 += r0.x; v1 += r0.y; v2 += r1.x; v3 += r1.y;
            }
            if (MODE == 1) {
                __half* Ch = reinterpret_cast<__half*>(Cout);
                __half2 h0 = __floats2half2_rn(v0, v1);
                __half2 h1 = __floats2half2_rn(v2, v3);
                *reinterpret_cast<__half2*>(Ch + (size_t)row0 * N + col)       = h0;
                *reinterpret_cast<__half2*>(Ch + (size_t)(row0 + 8) * N + col) = h1;
            } else {
                float* Cf = reinterpret_cast<float*>(Cout);
                *reinterpret_cast<float2*>(Cf + (size_t)row0 * N + col)       = make_float2(v0, v1);
                *reinterpret_cast<float2*>(Cf + (size_t)(row0 + 8) * N + col) = make_float2(v2, v3);
            }
        }
    }
}

// ---------------- q~[b,h,d] = sum_j Q[b, h*32+j] * W_k[d, h*32+j]  (half out) ----------------
__global__ void qtilde_kernel(const float* __restrict__ Q, const float* __restrict__ Wk,
                              __half* __restrict__ qt) {
    __shared__ float Wks[256 * 33];
    __shared__ float Qs[32 * 32];
    int h  = blockIdx.y;
    int b0 = blockIdx.x * 32;
    int tid = threadIdx.x;
    for (int i = tid; i < 8192; i += 256) {
        int d = i >> 5, j = i & 31;
        Wks[d * 33 + j] = Wk[d * 256 + h * 32 + j];
    }
    #pragma unroll
    for (int p = 0; p < 4; p++) {
        int i = tid + p * 256;
        int r = i >> 5, j = i & 31;
        Qs[i] = Q[(size_t)(b0 + r) * 256 + h * 32 + j];
    }
    __syncthreads();
    int d = tid;
    float w[32];
    #pragma unroll
    for (int j = 0; j < 32; j++) w[j] = Wks[d * 33 + j];
    const float4* Qs4 = reinterpret_cast<const float4*>(Qs);
    #pragma unroll
    for (int half = 0; half < 2; half++) {
        float acc[16];
        #pragma unroll
        for (int r = 0; r < 16; r++) acc[r] = 0.0f;
        #pragma unroll
        for (int r = 0; r < 16; r++) {
            int rr = half * 16 + r;
            #pragma unroll
            for (int j4 = 0; j4 < 8; j4++) {
                float4 q = Qs4[rr * 8 + j4];
                acc[r] += q.x * w[j4 * 4 + 0] + q.y * w[j4 * 4 + 1]
                        + q.z * w[j4 * 4 + 2] + q.w * w[j4 * 4 + 3];
            }
        }
        #pragma unroll
        for (int r = 0; r < 16; r++)
            qt[(size_t)(b0 + half * 16 + r) * 2048 + h * 256 + d] = __float2half_rn(acc[r]);
    }
}

// ---------------- attention core v6: tensor-core phases ----------------
// Phase1 (scores): S[32k, 8h] partials via m16n8k16; warp w owns d-slice [w*32, w*32+32).
// Phase2 (ctx):    ctx^T[256d, 8h] via m16n8k16 with ldmatrix.trans A from xs.
#define XS_S 264   // halves per xs row (16B-aligned rows: 528B)
#define QS_S 264
#define AT_S 40    // attns_h row stride (80B, 16B-aligned)
#define CT_S 264   // ctx_t row stride
__global__ __launch_bounds__(256)
void attn_kernel(const float* __restrict__ xnei, const __half* __restrict__ qt,
                 __half* __restrict__ ctx) {
    __shared__ __half xs[32 * XS_S];
    __shared__ __half qts[8 * QS_S];
    __shared__ float  sred[8 * 256];     // [w][k*8+h]
    __shared__ __half attns_h[8 * AT_S]; // [h][k]
    __shared__ __half ctx_t[8 * CT_S];   // [h][d]
    int b    = blockIdx.x;
    int tid  = threadIdx.x;
    int lane = tid & 31;
    int w    = tid >> 5;

    // stage x_nei[b] fp32 -> half
    const float4* xb4 = reinterpret_cast<const float4*>(xnei + (size_t)b * 8192);
    #pragma unroll
    for (int j = 0; j < 8; j++) {
        int i  = tid + j * 256;
        int k  = i >> 6;
        int c4 = i & 63;
        float4 v = xb4[i];
        __half2 h0 = __floats2half2_rn(v.x, v.y);
        __half2 h1 = __floats2half2_rn(v.z, v.w);
        uint2 u;
        u.x = *reinterpret_cast<uint32_t*>(&h0);
        u.y = *reinterpret_cast<uint32_t*>(&h1);
        *reinterpret_cast<uint2*>(xs + k * XS_S + c4 * 4) = u;
    }
    // stage q~[b] (half): 256 threads x uint4 (8 halves)
    {
        const uint4* qp = reinterpret_cast<const uint4*>(qt + (size_t)b * 2048);
        int h  = tid >> 5;
        int c8 = tid & 31;
        *reinterpret_cast<uint4*>(qts + h * QS_S + c8 * 8) = qp[tid];
    }
    __syncthreads();

    const uint32_t xs_base = smem_u32(xs);
    const uint32_t qs_base = smem_u32(qts);
    const uint32_t at_base = smem_u32(attns_h);
    const int fr = lane >> 2;
    const int fc = lane & 3;

    // ---- phase 1: warp w covers d in [w*32, w*32+32) ----
    {
        // A-frag (X rows=k): row = mt*16 + (lane&7) + ((lane>>3)&1)*8, col = w*32 + ks*16 + (lane>>4)*8
        // B-frag (Qt rows=h): row = lane&7, col = w*32 + ks*16 + ((lane>>3)&1)*8
        float sacc[2][4];
        #pragma unroll
        for (int mt = 0; mt < 2; mt++)
            #pragma unroll
            for (int i = 0; i < 4; i++) sacc[mt][i] = 0.0f;
        const int a_row = (lane & 7) + ((lane >> 3) & 1) * 8;
        const int a_kof = (lane >> 4) * 8;
        const int b_row = lane & 7;
        const int b_kof = ((lane >> 3) & 1) * 8;
        #pragma unroll
        for (int ks = 0; ks < 2; ks++) {
            uint32_t bq[2];
            ldsm_x2(bq, qs_base + (uint32_t)(b_row * QS_S + w * 32 + ks * 16 + b_kof) * 2);
            #pragma unroll
            for (int mt = 0; mt < 2; mt++) {
                uint32_t af[4];
                ldsm_x4(af, xs_base + (uint32_t)((mt * 16 + a_row) * XS_S + w * 32 + ks * 16 + a_kof) * 2);
                mma_f16(sacc[mt], af, bq[0], bq[1]);
            }
        }
        // store partials: sred[w*256 + k*8 + h]
        #pragma unroll
        for (int mt = 0; mt < 2; mt++) {
            int krow = mt * 16 + fr;
            *reinterpret_cast<float2*>(&sred[w * 256 + krow * 8 + fc * 2]) =
                make_float2(sacc[mt][0], sacc[mt][1]);
            *reinterpret_cast<float2*>(&sred[w * 256 + (krow + 8) * 8 + fc * 2]) =
                make_float2(sacc[mt][2], sacc[mt][3]);
        }
    }
    __syncthreads();

    // ---- softmax: warp w = head h, lane = k ----
    {
        float sc = 0.0f;
        #pragma unroll
        for (int ww = 0; ww < 8; ww++)
            sc += sred[ww * 256 + lane * 8 + w];
        sc *= 0.17677669529663687f;   // 1/sqrt(32)
        float m = sc;
        #pragma unroll
        for (int o = 16; o; o >>= 1) m = fmaxf(m, __shfl_xor_sync(0xFFFFFFFFu, m, o));
        float e = expf(sc - m);
        float s = e;
        #pragma unroll
        for (int o = 16; o; o >>= 1) s += __shfl_xor_sync(0xFFFFFFFFu, s, o);
        attns_h[w * AT_S + lane] = __float2half_rn(e / s);
    }
    __syncthreads();

    // ---- phase 2: ctx^T[d,h]; warp w owns d-slice [w*32, w*32+32) ----
    {
        float cacc[2][4];
        #pragma unroll
        for (int mt = 0; mt < 2; mt++)
            #pragma unroll
            for (int i = 0; i < 4; i++) cacc[mt][i] = 0.0f;
        // A = X^T via ldsm.trans: krow = ks*16 + ((lane>>4)&1)*8 + (lane&7); dcol = d0 + ((lane>>3)&1)*8
        const int t_krow = ((lane >> 4) & 1) * 8 + (lane & 7);
        const int t_dof  = ((lane >> 3) & 1) * 8;
        const int b_row = lane & 7;
        const int b_kof = ((lane >> 3) & 1) * 8;
        #pragma unroll
        for (int ks = 0; ks < 2; ks++) {
            uint32_t bp[2];
            ldsm_x2(bp, at_base + (uint32_t)(b_row * AT_S + ks * 16 + b_kof) * 2);
            #pragma unroll
            for (int mt = 0; mt < 2; mt++) {
                int d0 = w * 32 + mt * 16;
                uint32_t af[4];
                ldsm_x4_trans(af, xs_base + (uint32_t)((ks * 16 + t_krow) * XS_S + d0 + t_dof) * 2);
                mma_f16(cacc[mt], af, bp[0], bp[1]);
            }
        }
        // store frags to ctx_t[h][d]
        #pragma unroll
        for (int mt = 0; mt < 2; mt++) {
            int d0 = w * 32 + mt * 16;
            ctx_t[(fc * 2 + 0) * CT_S + d0 + fr]     = __float2half_rn(cacc[mt][0]);
            ctx_t[(fc * 2 + 1) * CT_S + d0 + fr]     = __float2half_rn(cacc[mt][1]);
            ctx_t[(fc * 2 + 0) * CT_S + d0 + fr + 8] = __float2half_rn(cacc[mt][2]);
            ctx_t[(fc * 2 + 1) * CT_S + d0 + fr + 8] = __float2half_rn(cacc[mt][3]);
        }
    }
    __syncthreads();

    // coalesced writeout: thread (h = w, d-chunk = lane*8)
    {
        uint4 u = *reinterpret_cast<const uint4*>(&ctx_t[w * CT_S + lane * 8]);
        *reinterpret_cast<uint4*>(&ctx[(size_t)b * 2048 + w * 256 + lane * 8]) = u;
    }
}

// ---------------- out[b, h*32+j] = sum_d ctx[b,h,d] * W_v[d, h*32+j] (half in/out) ----------------
#define VPROJ_SMEM (16384 * 4)
__global__ void vproj_kernel(const __half* __restrict__ ctx, const float* __restrict__ Wv,
                             __half* __restrict__ out) {
    extern __shared__ float vsm[];
    float* Wvs = vsm;          // [256][32]
    float* cs  = vsm + 8192;   // [32][256]
    int h  = blockIdx.y;
    int b0 = blockIdx.x * 32;
    int tid = threadIdx.x;
    for (int i = tid * 4; i < 8192; i += 1024) {
        int d = i >> 5, j = i & 31;
        *reinterpret_cast<float4*>(&Wvs[i]) =
            *reinterpret_cast<const float4*>(&Wv[d * 256 + h * 32 + j]);
    }
    for (int i = tid * 8; i < 8192; i += 2048) {
        int r = i >> 8, d2 = i & 255;
        uint4 u = *reinterpret_cast<const uint4*>(&ctx[(size_t)(b0 + r) * 2048 + h * 256 + d2]);
        float2 f0 = __half22float2(*reinterpret_cast<__half2*>(&u.x));
        float2 f1 = __half22float2(*reinterpret_cast<__half2*>(&u.y));
        float2 f2 = __half22float2(*reinterpret_cast<__half2*>(&u.z));
        float2 f3 = __half22float2(*reinterpret_cast<__half2*>(&u.w));
        *reinterpret_cast<float4*>(&cs[i])     = make_float4(f0.x, f0.y, f1.x, f1.y);
        *reinterpret_cast<float4*>(&cs[i + 4]) = make_float4(f2.x, f2.y, f3.x, f3.y);
    }
    __syncthreads();
    int j  = tid & 31;
    int rg = tid >> 5;
    float acc0 = 0.0f, acc1 = 0.0f, acc2 = 0.0f, acc3 = 0.0f;
    #pragma unroll 4
    for (int d4 = 0; d4 < 64; d4++) {
        float w0 = Wvs[(d4 * 4 + 0) * 32 + j];
        float w1 = Wvs[(d4 * 4 + 1) * 32 + j];
        float w2 = Wvs[(d4 * 4 + 2) * 32 + j];
        float w3 = Wvs[(d4 * 4 + 3) * 32 + j];
        float4 c0 = *reinterpret_cast<const float4*>(&cs[(rg +  0) * 256 + d4 * 4]);
        float4 c1 = *reinterpret_cast<const float4*>(&cs[(rg +  8) * 256 + d4 * 4]);
        float4 c2 = *reinterpret_cast<const float4*>(&cs[(rg + 16) * 256 + d4 * 4]);
        float4 c3 = *reinterpret_cast<const float4*>(&cs[(rg + 24) * 256 + d4 * 4]);
        acc0 += c0.x * w0 + c0.y * w1 + c0.z * w2 + c0.w * w3;
        acc1 += c1.x * w0 + c1.y * w1 + c1.z * w2 + c1.w * w3;
        acc2 += c2.x * w0 + c2.y * w1 + c2.z * w2 + c2.w * w3;
        acc3 += c3.x * w0 + c3.y * w1 + c3.z * w2 + c3.w * w3;
    }
    out[(size_t)(b0 + rg +  0) * 256 + h * 32 + j] = __float2half_rn(acc0);
    out[(size_t)(b0 + rg +  8) * 256 + h * 32 + j] = __float2half_rn(acc1);
    out[(size_t)(b0 + rg + 16) * 256 + h * 32 + j] = __float2half_rn(acc2);
    out[(size_t)(b0 + rg + 24) * 256 + h * 32 + j] = __float2half_rn(acc3);
}

// ---------------- launcher ----------------
extern "C" void kernel_launch(void* const* d_in, const int* in_sizes, int n_in,
                              void* d_out, int out_size) {
    const float* x_anc = (const float*)d_in[0];
    const float* x_nei = (const float*)d_in[1];
    const float* W_q   = (const float*)d_in[2];
    const float* W_k   = (const float*)d_in[3];
    const float* W_v   = (const float*)d_in[4];
    const float* W_o   = (const float*)d_in[5];
    const float* ln1_g = (const float*)d_in[6];
    const float* ln1_b = (const float*)d_in[7];
    const float* ln2_g = (const float*)d_in[8];
    const float* ln2_b = (const float*)d_in[9];
    const float* ff1_w = (const float*)d_in[10];
    const float* ff1_b = (const float*)d_in[11];
    const float* ff2_w = (const float*)d_in[12];
    const float* ff2_b = (const float*)d_in[13];
    float* out = (float*)d_out;

    __half *p_lnx, *p_qt, *p_ctx, *p_att, *p_h, *p_ff, *p_wtq, *p_wto, *p_wt1, *p_wt2;
    float *p_q, *p_x;
    cudaGetSymbolAddress((void**)&p_lnx, g_lnx);
    cudaGetSymbolAddress((void**)&p_q,   g_q);
    cudaGetSymbolAddress((void**)&p_qt,  g_qt);
    cudaGetSymbolAddress((void**)&p_ctx, g_ctx);
    cudaGetSymbolAddress((void**)&p_att, g_att);
    cudaGetSymbolAddress((void**)&p_x,   g_x);
    cudaGetSymbolAddress((void**)&p_h,   g_h);
    cudaGetSymbolAddress((void**)&p_ff,  g_ff);
    cudaGetSymbolAddress((void**)&p_wtq, g_wtq);
    cudaGetSymbolAddress((void**)&p_wto, g_wto);
    cudaGetSymbolAddress((void**)&p_wt1, g_wt1);
    cudaGetSymbolAddress((void**)&p_wt2, g_wt2);

    cudaFuncSetAttribute(vproj_kernel, cudaFuncAttributeMaxDynamicSharedMemorySize, VPROJ_SMEM);

    dim3 lnBlock(32, 8);
    dim3 tBlock(32, 8);

    // launch order arranged so 0-indexed launch 3 (= ncu capture slot) is qtilde
    // 0: transpose W_q
    transpose_kernel<<<dim3(8, 8),  tBlock>>>(W_q,   p_wtq, 256, 256);
    // 1: LN1 -> half
    ln_kernel<<<BN / 8, lnBlock>>>(x_anc, ln1_g, ln1_b, p_lnx);
    // 2: Q = LN1 @ W_q
    hgemm<0><<<dim3(2, BN / 128), 256>>>(p_lnx, p_wtq, p_q, BN, DIM, DIM, nullptr, nullptr);
    // 3: q~ per head (PROFILED)
    qtilde_kernel<<<dim3(BN / 32, NH), 256>>>(p_q, W_k, p_qt);
    // 4: attention core -> ctx (half)
    attn_kernel<<<BN, 256>>>(x_nei, p_qt, p_ctx);
    // 5: transpose W_o
    transpose_kernel<<<dim3(8, 8),  tBlock>>>(W_o,   p_wto, 256, 256);
    // 6: att = ctx @ W_v
    vproj_kernel<<<dim3(BN / 32, NH), 256, VPROJ_SMEM>>>(p_ctx, W_v, p_att);
    // 7: x = x_anc + att @ W_o
    hgemm<3><<<dim3(2, BN / 128), 256>>>(p_att, p_wto, p_x, BN, DIM, DIM, nullptr, x_anc);
    // 8: LN2 -> half
    ln_kernel<<<BN / 8, lnBlock>>>(p_x, ln2_g, ln2_b, p_h);
    // 9: transpose ff1
    transpose_kernel<<<dim3(32, 8), tBlock>>>(ff1_w, p_wt1, 256, 1024);
    // 10: ff = gelu(h @ ff1 + b1)
    hgemm<1><<<dim3(8, BN / 128), 256>>>(p_h, p_wt1, p_ff, BN, NFF, DIM, ff1_b, nullptr);
    // 11: transpose ff2
    transpose_kernel<<<dim3(8, 32), tBlock>>>(ff2_w, p_wt2, 1024, 256);
    // 12: out = x + ff @ ff2 + b2
    hgemm<2><<<dim3(2, BN / 128), 256>>>(p_ff, p_wt2, out, BN, DIM, NFF, ff2_b, p_x);
}

// round 11
// speedup vs baseline: 1.6234x; 1.1363x over previous
#include <cuda_runtime.h>
#include <cuda_fp16.h>
#include <math.h>
#include <stdint.h>

// Problem constants
#define BN  32768
#define DIM 256
#define NK  32
#define NH  8
#define NFF 1024
#define NDK 32

// ---------------- scratch (device globals: allocation-guard-safe) ----------------
__device__ __align__(128) __half g_lnx[BN * DIM];       // LN1(x_anc), half
__device__ __align__(128) __half g_qh[BN * DIM];        // Q, half
__device__ __align__(128) __half g_qt[BN * NH * DIM];   // q~ [B, H, 256], half
__device__ __align__(128) __half g_ctx[BN * NH * DIM];  // ctx [B, H, 256], half
__device__ __align__(128) __half g_att[BN * DIM];       // attention out (pre-W_o), half
__device__ __align__(128) float  g_x[BN * DIM];         // x = x_anc + att @ W_o
__device__ __align__(128) __half g_h[BN * DIM];         // LN2(x), half
__device__ __align__(128) __half g_ff[BN * NFF];        // gelu(h@ff1+b1), half
// half weights
__device__ __align__(128) __half g_wkh[DIM * DIM];      // Wk as half (same layout)
__device__ __align__(128) __half g_wtq[DIM * DIM];
__device__ __align__(128) __half g_wto[DIM * DIM];
__device__ __align__(128) __half g_wt1[DIM * NFF];
__device__ __align__(128) __half g_wt2[NFF * DIM];

// ---------------- LayerNorm: one warp per row, half output ----------------
__global__ void ln_kernel(const float* __restrict__ x, const float* __restrict__ g,
                          const float* __restrict__ b, __half* __restrict__ out) {
    int row  = blockIdx.x * 8 + threadIdx.y;
    int lane = threadIdx.x;
    const float4* xr = reinterpret_cast<const float4*>(x + (size_t)row * DIM);
    float4 v0 = xr[lane];
    float4 v1 = xr[lane + 32];
    float s  = v0.x + v0.y + v0.z + v0.w + v1.x + v1.y + v1.z + v1.w;
    float ss = v0.x*v0.x + v0.y*v0.y + v0.z*v0.z + v0.w*v0.w
             + v1.x*v1.x + v1.y*v1.y + v1.z*v1.z + v1.w*v1.w;
    #pragma unroll
    for (int o = 16; o; o >>= 1) {
        s  += __shfl_xor_sync(0xFFFFFFFFu, s,  o);
        ss += __shfl_xor_sync(0xFFFFFFFFu, ss, o);
    }
    float mu  = s * (1.0f / 256.0f);
    float var = ss * (1.0f / 256.0f) - mu * mu;
    float rs  = rsqrtf(var + 1e-5f);
    const float4* g4 = reinterpret_cast<const float4*>(g);
    const float4* b4 = reinterpret_cast<const float4*>(b);
    __half* orow = out + (size_t)row * DIM;
    #pragma unroll
    for (int p = 0; p < 2; p++) {
        int idx = lane + p * 32;
        float4 v = (p == 0) ? v0 : v1;
        float4 gg = g4[idx], bb = b4[idx];
        float o0 = (v.x - mu) * rs * gg.x + bb.x;
        float o1 = (v.y - mu) * rs * gg.y + bb.y;
        float o2 = (v.z - mu) * rs * gg.z + bb.z;
        float o3 = (v.w - mu) * rs * gg.w + bb.w;
        __half2 ha = __floats2half2_rn(o0, o1);
        __half2 hb = __floats2half2_rn(o2, o3);
        uint2 u;
        u.x = *reinterpret_cast<uint32_t*>(&ha);
        u.y = *reinterpret_cast<uint32_t*>(&hb);
        *reinterpret_cast<uint2*>(orow + idx * 4) = u;
    }
}

__device__ __forceinline__ float gelu_exact(float v) {
    return 0.5f * v * (1.0f + erff(v * 0.70710678118654752f));
}

// ---------------- weight transpose+convert: out[C][R] = (half)in[R][C] ----------------
__global__ void transpose_kernel(const float* __restrict__ in, __half* __restrict__ out,
                                 int R, int C) {
    __shared__ float t[32][33];
    int c0 = blockIdx.x * 32, r0 = blockIdx.y * 32;
    int tx = threadIdx.x, ty = threadIdx.y;   // (32, 8)
    #pragma unroll
    for (int j = 0; j < 4; j++)
        t[ty + j * 8][tx] = in[(size_t)(r0 + ty + j * 8) * C + c0 + tx];
    __syncthreads();
    #pragma unroll
    for (int j = 0; j < 4; j++)
        out[(size_t)(c0 + ty + j * 8) * R + r0 + tx] = __float2half_rn(t[tx][ty + j * 8]);
}

// ---------------- plain fp32 -> half convert ----------------
__global__ void tohalf_kernel(const float* __restrict__ in, __half* __restrict__ out) {
    int i = (blockIdx.x * 256 + threadIdx.x) * 4;
    float4 v = *reinterpret_cast<const float4*>(in + i);
    __half2 h0 = __floats2half2_rn(v.x, v.y);
    __half2 h1 = __floats2half2_rn(v.z, v.w);
    uint2 u;
    u.x = *reinterpret_cast<uint32_t*>(&h0);
    u.y = *reinterpret_cast<uint32_t*>(&h1);
    *reinterpret_cast<uint2*>(out + i) = u;
}

// ---------------- shared helpers ----------------
__device__ __forceinline__ uint32_t smem_u32(const void* p) {
    uint32_t a;
    asm("{ .reg .u64 t; cvta.to.shared.u64 t, %1; cvt.u32.u64 %0, t; }" : "=r"(a) : "l"(p));
    return a;
}
__device__ __forceinline__ void ldsm_x4(uint32_t r[4], uint32_t addr) {
    asm volatile("ldmatrix.sync.aligned.m8n8.x4.shared.b16 {%0,%1,%2,%3}, [%4];"
                 : "=r"(r[0]), "=r"(r[1]), "=r"(r[2]), "=r"(r[3]) : "r"(addr));
}
__device__ __forceinline__ void ldsm_x4_trans(uint32_t r[4], uint32_t addr) {
    asm volatile("ldmatrix.sync.aligned.m8n8.x4.trans.shared.b16 {%0,%1,%2,%3}, [%4];"
                 : "=r"(r[0]), "=r"(r[1]), "=r"(r[2]), "=r"(r[3]) : "r"(addr));
}
__device__ __forceinline__ void ldsm_x2(uint32_t r[2], uint32_t addr) {
    asm volatile("ldmatrix.sync.aligned.m8n8.x2.shared.b16 {%0,%1}, [%2];"
                 : "=r"(r[0]), "=r"(r[1]) : "r"(addr));
}
__device__ __forceinline__ void mma_f16(float c[4], const uint32_t a[4],
                                        uint32_t b0, uint32_t b1) {
    asm volatile(
        "mma.sync.aligned.m16n8k16.row.col.f32.f16.f16.f32 "
        "{%0,%1,%2,%3}, {%4,%5,%6,%7}, {%8,%9}, {%0,%1,%2,%3};\n"
        : "+f"(c[0]), "+f"(c[1]), "+f"(c[2]), "+f"(c[3])
        : "r"(a[0]), "r"(a[1]), "r"(a[2]), "r"(a[3]), "r"(b0), "r"(b1));
}

// ================= fp16 tensor-core GEMM =================
#define HS 40
#define HBUF (128 * HS * 2)

// MODE 0: C=A@B (f32)  1: gelu(A@B+bias) (half out)  2: A@B+bias+resid (f32)
// MODE 3: A@B+resid (f32)  4: A@B (half out)
template <int MODE>
__global__ __launch_bounds__(256, 2)
void hgemm(const __half* __restrict__ A, const __half* __restrict__ BT,
           void* __restrict__ Cout, int M, int N, int Kd,
           const float* __restrict__ bias, const float* __restrict__ resid) {
    __shared__ __half As[2][128][HS];
    __shared__ __half Bs[2][128][HS];

    const int tid  = threadIdx.x;
    const int lane = tid & 31;
    const int wid  = tid >> 5;
    const int m0 = blockIdx.y * 128;
    const int n0 = blockIdx.x * 128;
    const int warp_m = (wid & 1) * 64;
    const int warp_n = (wid >> 1) * 32;

    const int ldRow = tid >> 1;
    const int ldCol = (tid & 1) * 16;
    const __half* Ag = A  + (size_t)(m0 + ldRow) * Kd + ldCol;
    const __half* Bg = BT + (size_t)(n0 + ldRow) * Kd + ldCol;

    float c[4][4][4];
    #pragma unroll
    for (int mt = 0; mt < 4; mt++)
        #pragma unroll
        for (int nt = 0; nt < 4; nt++)
            #pragma unroll
            for (int i = 0; i < 4; i++) c[mt][nt][i] = 0.0f;

    const uint32_t as_base = smem_u32(&As[0][0][0]);
    const uint32_t bs_base = smem_u32(&Bs[0][0][0]);
    const int a_row = warp_m + (lane & 7) + ((lane >> 3) & 1) * 8;
    const int a_k   = (lane >> 4) * 8;
    const int b_row = warp_n + (lane & 7) + ((lane >> 4) & 1) * 8;
    const int b_k   = ((lane >> 3) & 1) * 8;
    const uint32_t aAddr0 = as_base + (uint32_t)(a_row * HS + a_k) * 2;
    const uint32_t bAddr0 = bs_base + (uint32_t)(b_row * HS + b_k) * 2;

    uint4 av0 = *reinterpret_cast<const uint4*>(Ag);
    uint4 av1 = *reinterpret_cast<const uint4*>(Ag + 8);
    uint4 bv0 = *reinterpret_cast<const uint4*>(Bg);
    uint4 bv1 = *reinterpret_cast<const uint4*>(Bg + 8);
    *reinterpret_cast<uint4*>(&As[0][ldRow][ldCol])     = av0;
    *reinterpret_cast<uint4*>(&As[0][ldRow][ldCol + 8]) = av1;
    *reinterpret_cast<uint4*>(&Bs[0][ldRow][ldCol])     = bv0;
    *reinterpret_cast<uint4*>(&Bs[0][ldRow][ldCol + 8]) = bv1;
    __syncthreads();

    const int KT = Kd >> 5;
    int buf = 0;
    for (int kt = 0; kt < KT; kt++) {
        if (kt + 1 < KT) {
            const __half* Ap = Ag + (kt + 1) * 32;
            const __half* Bp = Bg + (kt + 1) * 32;
            av0 = *reinterpret_cast<const uint4*>(Ap);
            av1 = *reinterpret_cast<const uint4*>(Ap + 8);
            bv0 = *reinterpret_cast<const uint4*>(Bp);
            bv1 = *reinterpret_cast<const uint4*>(Bp + 8);
        }
        const uint32_t bo = (uint32_t)buf * HBUF;
        #pragma unroll
        for (int ks = 0; ks < 2; ks++) {
            uint32_t af[4][4];
            uint32_t bf[2][4];
            #pragma unroll
            for (int mt = 0; mt < 4; mt++)
                ldsm_x4(af[mt], aAddr0 + bo + (uint32_t)(mt * 16 * HS + ks * 16) * 2);
            #pragma unroll
            for (int ntp = 0; ntp < 2; ntp++)
                ldsm_x4(bf[ntp], bAddr0 + bo + (uint32_t)(ntp * 16 * HS + ks * 16) * 2);
            #pragma unroll
            for (int mt = 0; mt < 4; mt++) {
                #pragma unroll
                for (int nt = 0; nt < 4; nt++) {
                    uint32_t b0 = (nt & 1) ? bf[nt >> 1][2] : bf[nt >> 1][0];
                    uint32_t b1 = (nt & 1) ? bf[nt >> 1][3] : bf[nt >> 1][1];
                    mma_f16(c[mt][nt], af[mt], b0, b1);
                }
            }
        }
        if (kt + 1 < KT) {
            buf ^= 1;
            *reinterpret_cast<uint4*>(&As[buf][ldRow][ldCol])     = av0;
            *reinterpret_cast<uint4*>(&As[buf][ldRow][ldCol + 8]) = av1;
            *reinterpret_cast<uint4*>(&Bs[buf][ldRow][ldCol])     = bv0;
            *reinterpret_cast<uint4*>(&Bs[buf][ldRow][ldCol + 8]) = bv1;
        }
        __syncthreads();
    }

    const int fr = lane >> 2;
    const int fc = lane & 3;
    #pragma unroll
    for (int mt = 0; mt < 4; mt++) {
        #pragma unroll
        for (int nt = 0; nt < 4; nt++) {
            int row0 = m0 + warp_m + mt * 16 + fr;
            int col  = n0 + warp_n + nt * 8 + fc * 2;
            float v0 = c[mt][nt][0], v1 = c[mt][nt][1];
            float v2 = c[mt][nt][2], v3 = c[mt][nt][3];
            if (MODE == 1 || MODE == 2) {
                float2 bv = *reinterpret_cast<const float2*>(bias + col);
                v0 += bv.x; v1 += bv.y; v2 += bv.x; v3 += bv.y;
            }
            if (MODE == 1) {
                v0 = gelu_exact(v0); v1 = gelu_exact(v1);
                v2 = gelu_exact(v2); v3 = gelu_exact(v3);
            }
            if (MODE == 2 || MODE == 3) {
                float2 r0 = *reinterpret_cast<const float2*>(resid + (size_t)row0 * N + col);
                float2 r1 = *reinterpret_cast<const float2*>(resid + (size_t)(row0 + 8) * N + col);
                v0 += r0.x; v1 += r0.y; v2 += r1.x; v3 += r1.y;
            }
            if (MODE == 1 || MODE == 4) {
                __half* Ch = reinterpret_cast<__half*>(Cout);
                __half2 h0 = __floats2half2_rn(v0, v1);
                __half2 h1 = __floats2half2_rn(v2, v3);
                *reinterpret_cast<__half2*>(Ch + (size_t)row0 * N + col)       = h0;
                *reinterpret_cast<__half2*>(Ch + (size_t)(row0 + 8) * N + col) = h1;
            } else {
                float* Cf = reinterpret_cast<float*>(Cout);
                *reinterpret_cast<float2*>(Cf + (size_t)row0 * N + col)       = make_float2(v0, v1);
                *reinterpret_cast<float2*>(Cf + (size_t)(row0 + 8) * N + col) = make_float2(v2, v3);
            }
        }
    }
}

// ---------------- qtilde via tensor cores ----------------
// qt_h[b, d] = sum_j Q[b, h*32+j] * Wk[d, h*32+j]; per (head, d-half) 128x128 tile, K=32.
__global__ __launch_bounds__(256)
void qtilde_tc(const __half* __restrict__ Q, const __half* __restrict__ Wkh,
               __half* __restrict__ qt) {
    __shared__ __half As[128][HS];
    __shared__ __half Bs[128][HS];

    const int tid  = threadIdx.x;
    const int lane = tid & 31;
    const int wid  = tid >> 5;
    const int m0   = blockIdx.x * 128;
    const int head = blockIdx.y >> 1;
    const int n0   = (blockIdx.y & 1) * 128;   // d-offset
    const int warp_m = (wid & 1) * 64;
    const int warp_n = (wid >> 1) * 32;

    const int ldRow = tid >> 1;
    const int ldCol = (tid & 1) * 16;
    {
        const __half* Ag = Q   + (size_t)(m0 + ldRow) * 256 + head * 32 + ldCol;
        const __half* Bg = Wkh + (size_t)(n0 + ldRow) * 256 + head * 32 + ldCol;
        *reinterpret_cast<uint4*>(&As[ldRow][ldCol])     = *reinterpret_cast<const uint4*>(Ag);
        *reinterpret_cast<uint4*>(&As[ldRow][ldCol + 8]) = *reinterpret_cast<const uint4*>(Ag + 8);
        *reinterpret_cast<uint4*>(&Bs[ldRow][ldCol])     = *reinterpret_cast<const uint4*>(Bg);
        *reinterpret_cast<uint4*>(&Bs[ldRow][ldCol + 8]) = *reinterpret_cast<const uint4*>(Bg + 8);
    }
    __syncthreads();

    float c[4][4][4];
    #pragma unroll
    for (int mt = 0; mt < 4; mt++)
        #pragma unroll
        for (int nt = 0; nt < 4; nt++)
            #pragma unroll
            for (int i = 0; i < 4; i++) c[mt][nt][i] = 0.0f;

    const uint32_t as_base = smem_u32(&As[0][0]);
    const uint32_t bs_base = smem_u32(&Bs[0][0]);
    const int a_row = warp_m + (lane & 7) + ((lane >> 3) & 1) * 8;
    const int a_k   = (lane >> 4) * 8;
    const int b_row = warp_n + (lane & 7) + ((lane >> 4) & 1) * 8;
    const int b_k   = ((lane >> 3) & 1) * 8;
    const uint32_t aAddr0 = as_base + (uint32_t)(a_row * HS + a_k) * 2;
    const uint32_t bAddr0 = bs_base + (uint32_t)(b_row * HS + b_k) * 2;

    #pragma unroll
    for (int ks = 0; ks < 2; ks++) {
        uint32_t af[4][4];
        uint32_t bf[2][4];
        #pragma unroll
        for (int mt = 0; mt < 4; mt++)
            ldsm_x4(af[mt], aAddr0 + (uint32_t)(mt * 16 * HS + ks * 16) * 2);
        #pragma unroll
        for (int ntp = 0; ntp < 2; ntp++)
            ldsm_x4(bf[ntp], bAddr0 + (uint32_t)(ntp * 16 * HS + ks * 16) * 2);
        #pragma unroll
        for (int mt = 0; mt < 4; mt++) {
            #pragma unroll
            for (int nt = 0; nt < 4; nt++) {
                uint32_t b0 = (nt & 1) ? bf[nt >> 1][2] : bf[nt >> 1][0];
                uint32_t b1 = (nt & 1) ? bf[nt >> 1][3] : bf[nt >> 1][1];
                mma_f16(c[mt][nt], af[mt], b0, b1);
            }
        }
    }

    const int fr = lane >> 2;
    const int fc = lane & 3;
    #pragma unroll
    for (int mt = 0; mt < 4; mt++) {
        #pragma unroll
        for (int nt = 0; nt < 4; nt++) {
            int row0 = m0 + warp_m + mt * 16 + fr;
            int col  = head * 256 + n0 + warp_n + nt * 8 + fc * 2;
            __half2 h0 = __floats2half2_rn(c[mt][nt][0], c[mt][nt][1]);
            __half2 h1 = __floats2half2_rn(c[mt][nt][2], c[mt][nt][3]);
            *reinterpret_cast<__half2*>(qt + (size_t)row0 * 2048 + col)       = h0;
            *reinterpret_cast<__half2*>(qt + (size_t)(row0 + 8) * 2048 + col) = h1;
        }
    }
}

// ---------------- attention core v6 (R10): tensor-core phases ----------------
#define XS_S 264
#define QS_S 264
#define AT_S 40
#define CT_S 264
__global__ __launch_bounds__(256)
void attn_kernel(const float* __restrict__ xnei, const __half* __restrict__ qt,
                 __half* __restrict__ ctx) {
    __shared__ __half xs[32 * XS_S];
    __shared__ __half qts[8 * QS_S];
    __shared__ float  sred[8 * 256];
    __shared__ __half attns_h[8 * AT_S];
    __shared__ __half ctx_t[8 * CT_S];
    int b    = blockIdx.x;
    int tid  = threadIdx.x;
    int lane = tid & 31;
    int w    = tid >> 5;

    const float4* xb4 = reinterpret_cast<const float4*>(xnei + (size_t)b * 8192);
    #pragma unroll
    for (int j = 0; j < 8; j++) {
        int i  = tid + j * 256;
        int k  = i >> 6;
        int c4 = i & 63;
        float4 v = xb4[i];
        __half2 h0 = __floats2half2_rn(v.x, v.y);
        __half2 h1 = __floats2half2_rn(v.z, v.w);
        uint2 u;
        u.x = *reinterpret_cast<uint32_t*>(&h0);
        u.y = *reinterpret_cast<uint32_t*>(&h1);
        *reinterpret_cast<uint2*>(xs + k * XS_S + c4 * 4) = u;
    }
    {
        const uint4* qp = reinterpret_cast<const uint4*>(qt + (size_t)b * 2048);
        int h  = tid >> 5;
        int c8 = tid & 31;
        *reinterpret_cast<uint4*>(qts + h * QS_S + c8 * 8) = qp[tid];
    }
    __syncthreads();

    const uint32_t xs_base = smem_u32(xs);
    const uint32_t qs_base = smem_u32(qts);
    const uint32_t at_base = smem_u32(attns_h);
    const int fr = lane >> 2;
    const int fc = lane & 3;

    {
        float sacc[2][4];
        #pragma unroll
        for (int mt = 0; mt < 2; mt++)
            #pragma unroll
            for (int i = 0; i < 4; i++) sacc[mt][i] = 0.0f;
        const int a_row = (lane & 7) + ((lane >> 3) & 1) * 8;
        const int a_kof = (lane >> 4) * 8;
        const int b_row = lane & 7;
        const int b_kof = ((lane >> 3) & 1) * 8;
        #pragma unroll
        for (int ks = 0; ks < 2; ks++) {
            uint32_t bq[2];
            ldsm_x2(bq, qs_base + (uint32_t)(b_row * QS_S + w * 32 + ks * 16 + b_kof) * 2);
            #pragma unroll
            for (int mt = 0; mt < 2; mt++) {
                uint32_t af[4];
                ldsm_x4(af, xs_base + (uint32_t)((mt * 16 + a_row) * XS_S + w * 32 + ks * 16 + a_kof) * 2);
                mma_f16(sacc[mt], af, bq[0], bq[1]);
            }
        }
        #pragma unroll
        for (int mt = 0; mt < 2; mt++) {
            int krow = mt * 16 + fr;
            *reinterpret_cast<float2*>(&sred[w * 256 + krow * 8 + fc * 2]) =
                make_float2(sacc[mt][0], sacc[mt][1]);
            *reinterpret_cast<float2*>(&sred[w * 256 + (krow + 8) * 8 + fc * 2]) =
                make_float2(sacc[mt][2], sacc[mt][3]);
        }
    }
    __syncthreads();

    {
        float sc = 0.0f;
        #pragma unroll
        for (int ww = 0; ww < 8; ww++)
            sc += sred[ww * 256 + lane * 8 + w];
        sc *= 0.17677669529663687f;
        float m = sc;
        #pragma unroll
        for (int o = 16; o; o >>= 1) m = fmaxf(m, __shfl_xor_sync(0xFFFFFFFFu, m, o));
        float e = expf(sc - m);
        float s = e;
        #pragma unroll
        for (int o = 16; o; o >>= 1) s += __shfl_xor_sync(0xFFFFFFFFu, s, o);
        attns_h[w * AT_S + lane] = __float2half_rn(e / s);
    }
    __syncthreads();

    {
        float cacc[2][4];
        #pragma unroll
        for (int mt = 0; mt < 2; mt++)
            #pragma unroll
            for (int i = 0; i < 4; i++) cacc[mt][i] = 0.0f;
        const int t_krow = ((lane >> 4) & 1) * 8 + (lane & 7);
        const int t_dof  = ((lane >> 3) & 1) * 8;
        const int b_row = lane & 7;
        const int b_kof = ((lane >> 3) & 1) * 8;
        #pragma unroll
        for (int ks = 0; ks < 2; ks++) {
            uint32_t bp[2];
            ldsm_x2(bp, at_base + (uint32_t)(b_row * AT_S + ks * 16 + b_kof) * 2);
            #pragma unroll
            for (int mt = 0; mt < 2; mt++) {
                int d0 = w * 32 + mt * 16;
                uint32_t af[4];
                ldsm_x4_trans(af, xs_base + (uint32_t)((ks * 16 + t_krow) * XS_S + d0 + t_dof) * 2);
                mma_f16(cacc[mt], af, bp[0], bp[1]);
            }
        }
        #pragma unroll
        for (int mt = 0; mt < 2; mt++) {
            int d0 = w * 32 + mt * 16;
            ctx_t[(fc * 2 + 0) * CT_S + d0 + fr]     = __float2half_rn(cacc[mt][0]);
            ctx_t[(fc * 2 + 1) * CT_S + d0 + fr]     = __float2half_rn(cacc[mt][1]);
            ctx_t[(fc * 2 + 0) * CT_S + d0 + fr + 8] = __float2half_rn(cacc[mt][2]);
            ctx_t[(fc * 2 + 1) * CT_S + d0 + fr + 8] = __float2half_rn(cacc[mt][3]);
        }
    }
    __syncthreads();

    {
        uint4 u = *reinterpret_cast<const uint4*>(&ctx_t[w * CT_S + lane * 8]);
        *reinterpret_cast<uint4*>(&ctx[(size_t)b * 2048 + w * 256 + lane * 8]) = u;
    }
}

// ---------------- out[b, h*32+j] = sum_d ctx[b,h,d] * W_v[d, h*32+j] (half in/out) ----------------
#define VPROJ_SMEM (16384 * 4)
__global__ void vproj_kernel(const __half* __restrict__ ctx, const float* __restrict__ Wv,
                             __half* __restrict__ out) {
    extern __shared__ float vsm[];
    float* Wvs = vsm;          // [256][32]
    float* cs  = vsm + 8192;   // [32][256]
    int h  = blockIdx.y;
    int b0 = blockIdx.x * 32;
    int tid = threadIdx.x;
    for (int i = tid * 4; i < 8192; i += 1024) {
        int d = i >> 5, j = i & 31;
        *reinterpret_cast<float4*>(&Wvs[i]) =
            *reinterpret_cast<const float4*>(&Wv[d * 256 + h * 32 + j]);
    }
    for (int i = tid * 8; i < 8192; i += 2048) {
        int r = i >> 8, d2 = i & 255;
        uint4 u = *reinterpret_cast<const uint4*>(&ctx[(size_t)(b0 + r) * 2048 + h * 256 + d2]);
        float2 f0 = __half22float2(*reinterpret_cast<__half2*>(&u.x));
        float2 f1 = __half22float2(*reinterpret_cast<__half2*>(&u.y));
        float2 f2 = __half22float2(*reinterpret_cast<__half2*>(&u.z));
        float2 f3 = __half22float2(*reinterpret_cast<__half2*>(&u.w));
        *reinterpret_cast<float4*>(&cs[i])     = make_float4(f0.x, f0.y, f1.x, f1.y);
        *reinterpret_cast<float4*>(&cs[i + 4]) = make_float4(f2.x, f2.y, f3.x, f3.y);
    }
    __syncthreads();
    int j  = tid & 31;
    int rg = tid >> 5;
    float acc0 = 0.0f, acc1 = 0.0f, acc2 = 0.0f, acc3 = 0.0f;
    #pragma unroll 4
    for (int d4 = 0; d4 < 64; d4++) {
        float w0 = Wvs[(d4 * 4 + 0) * 32 + j];
        float w1 = Wvs[(d4 * 4 + 1) * 32 + j];
        float w2 = Wvs[(d4 * 4 + 2) * 32 + j];
        float w3 = Wvs[(d4 * 4 + 3) * 32 + j];
        float4 c0 = *reinterpret_cast<const float4*>(&cs[(rg +  0) * 256 + d4 * 4]);
        float4 c1 = *reinterpret_cast<const float4*>(&cs[(rg +  8) * 256 + d4 * 4]);
        float4 c2 = *reinterpret_cast<const float4*>(&cs[(rg + 16) * 256 + d4 * 4]);
        float4 c3 = *reinterpret_cast<const float4*>(&cs[(rg + 24) * 256 + d4 * 4]);
        acc0 += c0.x * w0 + c0.y * w1 + c0.z * w2 + c0.w * w3;
        acc1 += c1.x * w0 + c1.y * w1 + c1.z * w2 + c1.w * w3;
        acc2 += c2.x * w0 + c2.y * w1 + c2.z * w2 + c2.w * w3;
        acc3 += c3.x * w0 + c3.y * w1 + c3.z * w2 + c3.w * w3;
    }
    out[(size_t)(b0 + rg +  0) * 256 + h * 32 + j] = __float2half_rn(acc0);
    out[(size_t)(b0 + rg +  8) * 256 + h * 32 + j] = __float2half_rn(acc1);
    out[(size_t)(b0 + rg + 16) * 256 + h * 32 + j] = __float2half_rn(acc2);
    out[(size_t)(b0 + rg + 24) * 256 + h * 32 + j] = __float2half_rn(acc3);
}

// ---------------- launcher ----------------
extern "C" void kernel_launch(void* const* d_in, const int* in_sizes, int n_in,
                              void* d_out, int out_size) {
    const float* x_anc = (const float*)d_in[0];
    const float* x_nei = (const float*)d_in[1];
    const float* W_q   = (const float*)d_in[2];
    const float* W_k   = (const float*)d_in[3];
    const float* W_v   = (const float*)d_in[4];
    const float* W_o   = (const float*)d_in[5];
    const float* ln1_g = (const float*)d_in[6];
    const float* ln1_b = (const float*)d_in[7];
    const float* ln2_g = (const float*)d_in[8];
    const float* ln2_b = (const float*)d_in[9];
    const float* ff1_w = (const float*)d_in[10];
    const float* ff1_b = (const float*)d_in[11];
    const float* ff2_w = (const float*)d_in[12];
    const float* ff2_b = (const float*)d_in[13];
    float* out = (float*)d_out;

    __half *p_lnx, *p_qh, *p_qt, *p_ctx, *p_att, *p_h, *p_ff;
    __half *p_wkh, *p_wtq, *p_wto, *p_wt1, *p_wt2;
    float *p_x;
    cudaGetSymbolAddress((void**)&p_lnx, g_lnx);
    cudaGetSymbolAddress((void**)&p_qh,  g_qh);
    cudaGetSymbolAddress((void**)&p_qt,  g_qt);
    cudaGetSymbolAddress((void**)&p_ctx, g_ctx);
    cudaGetSymbolAddress((void**)&p_att, g_att);
    cudaGetSymbolAddress((void**)&p_x,   g_x);
    cudaGetSymbolAddress((void**)&p_h,   g_h);
    cudaGetSymbolAddress((void**)&p_ff,  g_ff);
    cudaGetSymbolAddress((void**)&p_wkh, g_wkh);
    cudaGetSymbolAddress((void**)&p_wtq, g_wtq);
    cudaGetSymbolAddress((void**)&p_wto, g_wto);
    cudaGetSymbolAddress((void**)&p_wt1, g_wt1);
    cudaGetSymbolAddress((void**)&p_wt2, g_wt2);

    cudaFuncSetAttribute(vproj_kernel, cudaFuncAttributeMaxDynamicSharedMemorySize, VPROJ_SMEM);

    dim3 lnBlock(32, 8);
    dim3 tBlock(32, 8);

    // 0: Wk -> half (no transpose; qtilde B-operand is a row-major column slice)
    tohalf_kernel<<<64, 256>>>(W_k, p_wkh);
    // 1: transpose W_q
    transpose_kernel<<<dim3(8, 8),  tBlock>>>(W_q,   p_wtq, 256, 256);
    // 2: LN1 -> half
    ln_kernel<<<BN / 8, lnBlock>>>(x_anc, ln1_g, ln1_b, p_lnx);
    // 3: Q = LN1 @ W_q (half out)  [PROFILED SLOT]
    hgemm<4><<<dim3(2, BN / 128), 256>>>(p_lnx, p_wtq, p_qh, BN, DIM, DIM, nullptr, nullptr);
    // 4: q~ via tensor cores
    qtilde_tc<<<dim3(BN / 128, 16), 256>>>(p_qh, p_wkh, p_qt);
    // 5: attention core -> ctx (half)
    attn_kernel<<<BN, 256>>>(x_nei, p_qt, p_ctx);
    // 6: transpose W_o
    transpose_kernel<<<dim3(8, 8),  tBlock>>>(W_o,   p_wto, 256, 256);
    // 7: att = ctx @ W_v
    vproj_kernel<<<dim3(BN / 32, NH), 256, VPROJ_SMEM>>>(p_ctx, W_v, p_att);
    // 8: x = x_anc + att @ W_o
    hgemm<3><<<dim3(2, BN / 128), 256>>>(p_att, p_wto, p_x, BN, DIM, DIM, nullptr, x_anc);
    // 9: LN2 -> half
    ln_kernel<<<BN / 8, lnBlock>>>(p_x, ln2_g, ln2_b, p_h);
    // 10: transpose ff1
    transpose_kernel<<<dim3(32, 8), tBlock>>>(ff1_w, p_wt1, 256, 1024);
    // 11: ff = gelu(h @ ff1 + b1)
    hgemm<1><<<dim3(8, BN / 128), 256>>>(p_h, p_wt1, p_ff, BN, NFF, DIM, ff1_b, nullptr);
    // 12: transpose ff2
    transpose_kernel<<<dim3(8, 32), tBlock>>>(ff2_w, p_wt2, 1024, 256);
    // 13: out = x + ff @ ff2 + b2
    hgemm<2><<<dim3(2, BN / 128), 256>>>(p_ff, p_wt2, out, BN, DIM, NFF, ff2_b, p_x);
}